// round 13
// baseline (speedup 1.0000x reference)
#include <cuda_runtime.h>
#include <cuda_fp16.h>
#include <math.h>
#include <stdint.h>

#define BB   16
#define CC   256
#define ICC  64
#define HH   56
#define PP   (HH*HH)
#define OUTH 58
#define EPSV 1e-5f
#define SCALEV (1.0f/896.0f)

#define NXE (BB*CC*PP)

// ---------------- scratch ----------------
__device__ __half g_xH [2*NXE];
__device__ __half g_t1H[BB*ICC*PP];
__device__ __half g_lqh[BB*CC*PP];
__device__ __half g_kv [2*BB*2*CC*PP];
__device__ __half g_fH [BB*CC*PP];
__device__ float  g_xbar[BB*CC];
__device__ float  g_gqs [BB*CC];
__device__ __half g_wh  [2*512*256 + 2*64*256 + 256*256];
__device__ float  g_sb  [1024];

#define EPI_PAD    4
#define EPI_BIAS_H 5
#define EPI_BN_H   6
#define EPI_BNLR_H 7

__device__ __forceinline__ uint32_t smem_u32(const void* p){
    uint32_t a;
    asm("{ .reg .u64 t; cvta.to.shared.u64 t, %1; cvt.u32.u64 %0, t; }":"=r"(a):"l"(p));
    return a;
}
__device__ __forceinline__ void mma16(float c[4],
    uint32_t a0, uint32_t a1, uint32_t a2, uint32_t a3, uint32_t b0, uint32_t b1){
    asm volatile(
        "mma.sync.aligned.m16n8k16.row.col.f32.f16.f16.f32 "
        "{%0,%1,%2,%3}, {%4,%5,%6,%7}, {%8,%9}, {%0,%1,%2,%3};"
        : "+f"(c[0]),"+f"(c[1]),"+f"(c[2]),"+f"(c[3])
        : "r"(a0),"r"(a1),"r"(a2),"r"(a3),"r"(b0),"r"(b1));
}
__device__ __forceinline__ void ldsm4(uint32_t& r0, uint32_t& r1, uint32_t& r2, uint32_t& r3,
                                      uint32_t addr){
    asm volatile("ldmatrix.sync.aligned.m8n8.x4.shared.b16 {%0,%1,%2,%3}, [%4];"
        : "=r"(r0),"=r"(r1),"=r"(r2),"=r"(r3) : "r"(addr));
}
__device__ __forceinline__ void ldsm4t(uint32_t& r0, uint32_t& r1, uint32_t& r2, uint32_t& r3,
                                       uint32_t addr){
    asm volatile("ldmatrix.sync.aligned.m8n8.x4.trans.shared.b16 {%0,%1,%2,%3}, [%4];"
        : "=r"(r0),"=r"(r1),"=r"(r2),"=r"(r3) : "r"(addr));
}

// ================= fp16 tensor-core batched GEMM =================
// 128 threads, warp tile 64x64 (BM=128) / 64x32 (BM=64). BK=64, dynamic smem,
// double-buffered cp.async. Reg-capped for 3 CTAs/SM.
template<int BM, int EPI>
__global__ __launch_bounds__(128, 3)
void hgemm(const __half* __restrict__ W, const __half* __restrict__ X,
           void* __restrict__ Yv, int K, int Mtot,
           const float* __restrict__ bias,
           const float* __restrict__ gamma,
           const float* __restrict__ beta,
           size_t wstride, size_t xstride, size_t ystride, int bstride)
{
    constexpr int BN = 128, BK = 64;
    constexpr int WM = (BM == 128) ? 2 : 1;
    constexpr int WN = 4 / WM;
    constexpr int MT = 4;
    constexpr int NT = BN / (WN * 8);
    constexpr int ASTR = 72;
    constexpr int BSTR = 136;
    constexpr int ASZ = BM * ASTR;
    constexpr int BSZ = BK * BSTR;

    extern __shared__ __align__(16) __half dsm[];
    __half* sA = dsm;
    __half* sB = dsm + 2*ASZ;

    const int tid = threadIdx.x, wid = tid >> 5, lane = tid & 31;
    const int gid = lane >> 2, tig = lane & 3;
    const int l8 = lane & 7, lb1 = (lane >> 3) & 1, lb2 = lane >> 4;
    const int warpM = wid / WN, warpN = wid - warpM * WN;
    const int m0 = blockIdx.y * BM, n0 = blockIdx.x * BN;
    const int which = blockIdx.z / BB;
    const int b = blockIdx.z - which * BB;

    const __half* Wt = W + which*wstride + (size_t)m0 * K;
    const __half* Xb = X + which*xstride + (size_t)b * K * PP;
    const float* biasW = bias + which * bstride;
    const uint32_t sAb = smem_u32(sA);
    const uint32_t sBb = smem_u32(sB);

    float c[MT][NT][4];
    #pragma unroll
    for(int m=0;m<MT;m++)
        #pragma unroll
        for(int n=0;n<NT;n++)
            #pragma unroll
            for(int q=0;q<4;q++) c[m][n][q]=0.f;

    const int NK = K >> 6;

    auto load_tile = [&](int kt, int s){
        #pragma unroll
        for(int i = tid; i < BM*8; i += 128){
            int m = i >> 3, k8 = (i & 7) << 3;
            uint32_t dst = sAb + (s*ASZ + m*ASTR + k8) * 2;
            asm volatile("cp.async.cg.shared.global [%0], [%1], 16;"
                :: "r"(dst), "l"(Wt + (size_t)m*K + kt*64 + k8));
        }
        #pragma unroll
        for(int i = tid; i < 1024; i += 128){
            int kr = i >> 4, c8 = (i & 15) << 3;
            int p = n0 + c8;
            const __half* src = (p < PP) ? (Xb + (size_t)(kt*64 + kr)*PP + p) : Xb;
            uint32_t sz = (p < PP) ? 16u : 0u;
            uint32_t dst = sBb + (s*BSZ + kr*BSTR + c8) * 2;
            asm volatile("cp.async.cg.shared.global [%0], [%1], 16, %2;"
                :: "r"(dst), "l"(src), "r"(sz));
        }
        asm volatile("cp.async.commit_group;" ::: "memory");
    };

    load_tile(0, 0);

    for(int kt = 0; kt < NK; kt++){
        const int s = kt & 1;
        if(kt + 1 < NK){
            load_tile(kt + 1, 1 - s);
            asm volatile("cp.async.wait_group 1;" ::: "memory");
        } else {
            asm volatile("cp.async.wait_group 0;" ::: "memory");
        }
        __syncthreads();

        const uint32_t aBase = sAb + s*ASZ*2;
        const uint32_t bBase = sBb + s*BSZ*2;
        #pragma unroll
        for(int kk = 0; kk < BK; kk += 16){
            uint32_t a[MT][4], bb[NT][2];
            #pragma unroll
            for(int m=0;m<MT;m++){
                int mr = warpM*64 + m*16;
                uint32_t addr = aBase + (uint32_t)(((mr + l8 + lb1*8)*ASTR + kk + lb2*8)*2);
                ldsm4(a[m][0],a[m][1],a[m][2],a[m][3], addr);
            }
            #pragma unroll
            for(int np=0; np<NT/2; np++){
                int nc = warpN*(NT*8) + np*16;
                uint32_t addr = bBase + (uint32_t)(((kk + lb1*8 + l8)*BSTR + nc + lb2*8)*2);
                ldsm4t(bb[2*np][0], bb[2*np][1], bb[2*np+1][0], bb[2*np+1][1], addr);
            }
            #pragma unroll
            for(int m=0;m<MT;m++)
                #pragma unroll
                for(int n=0;n<NT;n++)
                    mma16(c[m][n], a[m][0],a[m][1],a[m][2],a[m][3], bb[n][0],bb[n][1]);
        }
        __syncthreads();
    }

    const float rs = rsqrtf(1.0f + EPSV);
    #pragma unroll
    for(int m=0;m<MT;m++){
        #pragma unroll
        for(int half_=0; half_<2; half_++){
            const int row = m0 + warpM*64 + m*16 + gid + half_*8;
            float add0=0.f, sc=1.f, sh=0.f;
            if(EPI==EPI_BIAS_H || EPI==EPI_PAD) add0=biasW[row];
            if(EPI==EPI_BN_H || EPI==EPI_BNLR_H){
                add0=biasW[row]; sc=gamma[row]*rs; sh=beta[row];
            }
            #pragma unroll
            for(int n=0;n<NT;n++){
                const int p = n0 + warpN*(NT*8) + n*8 + 2*tig;
                if(p < PP){
                    float y0 = c[m][n][half_*2+0];
                    float y1 = c[m][n][half_*2+1];
                    if(EPI==EPI_PAD){
                        float* Y = (float*)Yv;
                        y0 += add0; y1 += add0;
                        int h=p/HH, w=p-h*HH;
                        float* yb = Y + ((size_t)(b*CC+row)*OUTH)*OUTH;
                        yb[(h+1)*OUTH + w+1] = y0;
                        int p1=p+1, h1=p1/HH, w1=p1-h1*HH;
                        yb[(h1+1)*OUTH + w1+1] = y1;
                    } else {
                        if(EPI==EPI_BIAS_H){ y0+=add0; y1+=add0; }
                        if(EPI==EPI_BN_H){ y0=(y0+add0)*sc+sh; y1=(y1+add0)*sc+sh; }
                        if(EPI==EPI_BNLR_H){
                            y0=(y0+add0)*sc+sh; y0=(y0>=0.f)?y0:0.2f*y0;
                            y1=(y1+add0)*sc+sh; y1=(y1>=0.f)?y1:0.2f*y1;
                        }
                        __half* Yh = (__half*)Yv + which*ystride;
                        *reinterpret_cast<__half2*>(Yh + ((size_t)b*Mtot + row)*PP + p)
                            = __floats2half2_rn(y0, y1);
                    }
                }
            }
        }
    }
}

// ================= tensor-core attention =================
__global__ __launch_bounds__(128)
void attn_tc(const __half* __restrict__ lqh, const __half* __restrict__ kvsh,
             const __half* __restrict__ kvfqh, const float* __restrict__ gqs,
             __half* __restrict__ fH)
{
    constexpr int STR = 72;
    __shared__ __align__(16) __half sm[5*64*STR];
    __half* sQ  = sm;
    __half* sK  = sm + 1*64*STR;
    __half* sGK = sm + 2*64*STR;
    __half* sV  = sm + 3*64*STR;
    __half* sGV = sm + 4*64*STR;

    const int bc = blockIdx.x;
    const int b = bc >> 8, ch = bc & 255;
    const size_t base_q = (size_t)bc * PP;
    const size_t base_k = ((size_t)(b*512 + ch)) * PP;
    const size_t base_v = base_k + (size_t)256 * PP;
    const int tid = threadIdx.x, wid = tid>>5, lane = tid&31;
    const int gid = lane>>2, tig = lane&3;
    const int l8 = lane&7, lb1 = (lane>>3)&1, lb2 = lane>>4;

    const __half* srcs[5] = { lqh + base_q, kvsh + base_k, kvfqh + base_k,
                              kvsh + base_v, kvfqh + base_v };
    uint32_t* usm = (uint32_t*)sm;

    for(int i = tid; i < 5*64*4; i += 128){
        int arr = i >> 8, rem = i & 255;
        int r = rem >> 2, j = rem & 3;
        usm[arr*64*36 + r*36 + 28 + j] = 0;
    }
    for(int i = tid; i < 5*8*28; i += 128){
        int arr = i / 224, rem = i - arr*224;
        int r = 56 + rem/28, j = rem - (rem/28)*28;
        usm[arr*64*36 + r*36 + j] = 0;
    }
    const uint32_t smB = smem_u32(sm);
    #pragma unroll
    for(int arr = 0; arr < 5; arr++){
        for(int i = tid; i < 56*7; i += 128){
            int r = i/7, chx = i - r*7;
            uint32_t dst = smB + (arr*64*STR + r*STR + chx*8)*2;
            asm volatile("cp.async.cg.shared.global [%0], [%1], 16;"
                :: "r"(dst), "l"(srcs[arr] + (size_t)r*HH + chx*8));
        }
    }
    asm volatile("cp.async.commit_group;" ::: "memory");
    asm volatile("cp.async.wait_group 0;" ::: "memory");
    __syncthreads();

    const uint32_t qB = smem_u32(sQ), kB = smem_u32(sK), vB = smem_u32(sV);
    const uint32_t gkB = smem_u32(sGK), gvB = smem_u32(sGV);
    const int m0 = wid*16;
    const uint32_t aOff = (uint32_t)(((m0 + l8 + lb1*8)*STR)*2);
    const uint32_t bRowN = (uint32_t)((l8 + lb2*8)*STR*2);

    float c[8][4];
    #pragma unroll
    for(int n=0;n<8;n++){ c[n][0]=0; c[n][1]=0; c[n][2]=0; c[n][3]=0; }
    #pragma unroll
    for(int kk = 0; kk < 64; kk += 16){
        uint32_t a0,a1,a2,a3;
        ldsm4(a0,a1,a2,a3, qB + aOff + (kk + lb2*8)*2);
        uint32_t bb[8][2];
        #pragma unroll
        for(int np=0;np<4;np++){
            uint32_t addr = kB + bRowN + (uint32_t)((np*16*STR + kk + lb1*8)*2);
            ldsm4(bb[2*np][0], bb[2*np][1], bb[2*np+1][0], bb[2*np+1][1], addr);
        }
        #pragma unroll
        for(int n=0;n<8;n++)
            mma16(c[n], a0,a1,a2,a3, bb[n][0], bb[n][1]);
    }
    __syncthreads();

    #pragma unroll
    for(int half_=0; half_<2; half_++){
        const int h2 = half_*2;
        float m = -1e30f;
        #pragma unroll
        for(int n=0;n<7;n++) m = fmaxf(m, fmaxf(c[n][h2], c[n][h2+1]));
        m = fmaxf(m, __shfl_xor_sync(0xffffffffu, m, 1));
        m = fmaxf(m, __shfl_xor_sync(0xffffffffu, m, 2));
        float s = 0.f;
        #pragma unroll
        for(int n=0;n<7;n++){
            float e0 = __expf((c[n][h2  ] - m)*SCALEV);
            float e1 = __expf((c[n][h2+1] - m)*SCALEV);
            c[n][h2]=e0; c[n][h2+1]=e1; s += e0+e1;
        }
        s += __shfl_xor_sync(0xffffffffu, s, 1);
        s += __shfl_xor_sync(0xffffffffu, s, 2);
        const float inv = 1.f/s;
        const int row = m0 + gid + half_*8;
        #pragma unroll
        for(int n=0;n<8;n++){
            __half2 hv = (n<7) ? __floats2half2_rn(c[n][h2]*inv, c[n][h2+1]*inv)
                               : __floats2half2_rn(0.f, 0.f);
            *reinterpret_cast<__half2*>(sQ + row*STR + n*8 + 2*tig) = hv;
        }
    }

    if(tid < 56){
        const float gq = gqs[bc];
        __half* row = sGK + tid*STR;
        float m = -1e30f;
        for(int k=0;k<56;k++) m = fmaxf(m, gq*__half2float(row[k]));
        float s = 0.f;
        for(int k=0;k<56;k++){
            float e = __expf(gq*__half2float(row[k]) - m);
            row[k] = __float2half(e);
            s += e;
        }
        const float inv = 1.f/s;
        for(int k=0;k<56;k++)
            row[k] = __float2half(__half2float(row[k])*inv);
        uint32_t* ur = (uint32_t*)row;
        ur[28]=0; ur[29]=0; ur[30]=0; ur[31]=0;
    }
    __syncthreads();

    #pragma unroll
    for(int n=0;n<8;n++){ c[n][0]=0; c[n][1]=0; c[n][2]=0; c[n][3]=0; }
    #pragma unroll
    for(int kk = 0; kk < 64; kk += 16){
        uint32_t a0,a1,a2,a3;
        ldsm4(a0,a1,a2,a3, qB + aOff + (kk + lb2*8)*2);
        uint32_t bb[8][2];
        #pragma unroll
        for(int np=0;np<4;np++){
            int nc = np*16;
            uint32_t addr = vB + (uint32_t)(((kk + lb1*8 + l8)*STR + nc + lb2*8)*2);
            ldsm4t(bb[2*np][0], bb[2*np][1], bb[2*np+1][0], bb[2*np+1][1], addr);
        }
        #pragma unroll
        for(int n=0;n<8;n++)
            mma16(c[n], a0,a1,a2,a3, bb[n][0], bb[n][1]);
    }
    #pragma unroll
    for(int kk = 0; kk < 64; kk += 16){
        uint32_t a0,a1,a2,a3;
        ldsm4(a0,a1,a2,a3, gkB + aOff + (kk + lb2*8)*2);
        uint32_t bb[8][2];
        #pragma unroll
        for(int np=0;np<4;np++){
            int nc = np*16;
            uint32_t addr = gvB + (uint32_t)(((kk + lb1*8 + l8)*STR + nc + lb2*8)*2);
            ldsm4t(bb[2*np][0], bb[2*np][1], bb[2*np+1][0], bb[2*np+1][1], addr);
        }
        #pragma unroll
        for(int n=0;n<8;n++)
            mma16(c[n], a0,a1,a2,a3, bb[n][0], bb[n][1]);
    }

    #pragma unroll
    for(int half_=0; half_<2; half_++){
        const int row = m0 + gid + half_*8;
        if(row < 56){
            #pragma unroll
            for(int n=0;n<7;n++){
                *reinterpret_cast<__half2*>(fH + base_q + row*HH + n*8 + 2*tig)
                    = __floats2half2_rn(c[n][half_*2], c[n][half_*2+1]);
            }
        }
    }
}

// ---------------- fp32 -> half streaming convert ----------------
__global__ void cvt_pair(const float* __restrict__ a, const float* __restrict__ bsrc,
                         __half* __restrict__ dst)
{
    const int idx = blockIdx.x*256 + threadIdx.x;
    const int N4 = NXE/4;
    if(idx < N4){
        float4 v = reinterpret_cast<const float4*>(a)[idx];
        __half2 h0 = __floats2half2_rn(v.x, v.y);
        __half2 h1 = __floats2half2_rn(v.z, v.w);
        uint2 o;
        o.x = *reinterpret_cast<uint32_t*>(&h0);
        o.y = *reinterpret_cast<uint32_t*>(&h1);
        reinterpret_cast<uint2*>(dst)[idx] = o;

        float4 w = reinterpret_cast<const float4*>(bsrc)[idx];
        __half2 g0 = __floats2half2_rn(w.x, w.y);
        __half2 g1 = __floats2half2_rn(w.z, w.w);
        uint2 o2;
        o2.x = *reinterpret_cast<uint32_t*>(&g0);
        o2.y = *reinterpret_cast<uint32_t*>(&g1);
        reinterpret_cast<uint2*>(dst + NXE)[idx] = o2;
    }
}

// ---------------- weight prep ----------------
__global__ void prep_kernel(const float* __restrict__ lk_w, const float* __restrict__ lv_w,
                            const float* __restrict__ gk_w, const float* __restrict__ gv_w,
                            const float* __restrict__ la_w1, const float* __restrict__ la_w2,
                            const float* __restrict__ c1_w,
                            const float* __restrict__ lk_b, const float* __restrict__ gk_b,
                            __half* __restrict__ wh, float* __restrict__ sb)
{
    const int i = blockIdx.x*256 + threadIdx.x;
    if(i < 131072){
        wh[i]          = __float2half(i < 65536 ? lk_w[i] : lv_w[i-65536]);
        wh[131072 + i] = __float2half(i < 65536 ? gk_w[i] : gv_w[i-65536]);
    } else if(i < 147456){
        int j = i - 131072;
        wh[262144 + j] = __float2half(la_w1[j]);
        wh[278528 + j] = __float2half(la_w2[j]);
    }
    if(i < 65536) wh[294912 + i] = __float2half(c1_w[i]);
    if(i < 512){
        sb[i]       = (i < 256) ? lk_b[i] : 0.f;
        sb[512 + i] = (i < 256) ? gk_b[i] : 0.f;
    }
}

// ---------------- border fill ----------------
__global__ void border_fill_kernel(float* __restrict__ out, const float* __restrict__ bias)
{
    const int idx = blockIdx.x*256 + threadIdx.x;
    const int total = BB*CC*228;
    if(idx >= total) return;
    const int bc = idx / 228, j = idx - bc*228;
    int h, w;
    if(j < 58){ h = 0; w = j; }
    else if(j < 116){ h = 57; w = j - 58; }
    else { int j2 = j - 116; h = 1 + (j2 >> 1); w = (j2 & 1) * 57; }
    out[((size_t)bc*OUTH + h)*OUTH + w] = bias[bc & 255];
}

// ---------------- per-(b,c) mean ----------------
__global__ void mean_kernel(const float* __restrict__ x, float* __restrict__ xbar)
{
    __shared__ float red[256];
    const int bc=blockIdx.x;
    const float* p = x + (size_t)bc*PP;
    float s=0.f;
    for(int i=threadIdx.x;i<PP;i+=256) s+=p[i];
    red[threadIdx.x]=s; __syncthreads();
    for(int o=128;o>0;o>>=1){ if(threadIdx.x<o) red[threadIdx.x]+=red[threadIdx.x+o]; __syncthreads(); }
    if(threadIdx.x==0) xbar[bc]=red[0]*(1.0f/PP);
}

// ---------------- global-branch query MLP ----------------
__global__ void gq_kernel(const float* __restrict__ xbar,
                          const float* __restrict__ c11_w, const float* __restrict__ c11_b,
                          const float* __restrict__ ga_w1, const float* __restrict__ ga_b1,
                          const float* __restrict__ ga_g1, const float* __restrict__ ga_be1,
                          const float* __restrict__ ga_w2, const float* __restrict__ ga_b2,
                          const float* __restrict__ ga_g2, const float* __restrict__ ga_be2,
                          float* __restrict__ gqs)
{
    __shared__ float xb[CC], pv[CC], tv[ICC];
    const int b=blockIdx.x, t=threadIdx.x;
    const float rs=rsqrtf(1.0f+EPSV);
    xb[t]=xbar[b*CC+t]; __syncthreads();
    { float d=0.f; const float* wr=c11_w+(size_t)t*CC;
      for(int c=0;c<CC;c++) d=fmaf(wr[c],xb[c],d);
      pv[t]=d+c11_b[t]; }
    __syncthreads();
    if(t<ICC){ float d=0.f; const float* wr=ga_w1+(size_t)t*CC;
      for(int c=0;c<CC;c++) d=fmaf(wr[c],pv[c],d);
      d=(d+ga_b1[t])*(ga_g1[t]*rs)+ga_be1[t];
      tv[t]=(d>=0.f)?d:0.2f*d; }
    __syncthreads();
    { float d=0.f; const float* wr=ga_w2+(size_t)t*ICC;
      for(int i=0;i<ICC;i++) d=fmaf(wr[i],tv[i],d);
      d=(d+ga_b2[t])*(ga_g2[t]*rs)+ga_be2[t];
      gqs[b*CC+t]=d*SCALEV; }
}

// ---------------- launch ----------------
extern "C" void kernel_launch(void* const* d_in, const int* in_sizes, int n_in,
                              void* d_out, int out_size)
{
    const float* x_s  =(const float*)d_in[0];
    const float* x_fq =(const float*)d_in[1];
    const float* x_mt =(const float*)d_in[2];
    const float* la_w1=(const float*)d_in[3];
    const float* la_b1=(const float*)d_in[4];
    const float* la_g1=(const float*)d_in[5];
    const float* la_be1=(const float*)d_in[6];
    const float* la_w2=(const float*)d_in[7];
    const float* la_b2=(const float*)d_in[8];
    const float* la_g2=(const float*)d_in[9];
    const float* la_be2=(const float*)d_in[10];
    const float* lk_w =(const float*)d_in[11];
    const float* lk_b =(const float*)d_in[12];
    const float* lv_w =(const float*)d_in[13];
    const float* ga_w1=(const float*)d_in[14];
    const float* ga_b1=(const float*)d_in[15];
    const float* ga_g1=(const float*)d_in[16];
    const float* ga_be1=(const float*)d_in[17];
    const float* ga_w2=(const float*)d_in[18];
    const float* ga_b2=(const float*)d_in[19];
    const float* ga_g2=(const float*)d_in[20];
    const float* ga_be2=(const float*)d_in[21];
    const float* gk_w =(const float*)d_in[22];
    const float* gk_b =(const float*)d_in[23];
    const float* gv_w =(const float*)d_in[24];
    const float* c11_w=(const float*)d_in[25];
    const float* c11_b=(const float*)d_in[26];
    const float* c1_w =(const float*)d_in[27];
    const float* c1_b =(const float*)d_in[28];
    float* out=(float*)d_out;

    __half *xH,*t1H,*lqh,*kv,*fH,*wh;
    float *xbar,*gqs,*sb;
    cudaGetSymbolAddress((void**)&xH,  g_xH);
    cudaGetSymbolAddress((void**)&t1H, g_t1H);
    cudaGetSymbolAddress((void**)&lqh, g_lqh);
    cudaGetSymbolAddress((void**)&kv,  g_kv);
    cudaGetSymbolAddress((void**)&fH,  g_fH);
    cudaGetSymbolAddress((void**)&xbar,g_xbar);
    cudaGetSymbolAddress((void**)&gqs, g_gqs);
    cudaGetSymbolAddress((void**)&wh,  g_wh);
    cudaGetSymbolAddress((void**)&sb,  g_sb);

    __half* wh_kvs  = wh;
    __half* wh_la1  = wh + 262144;
    __half* wh_la2  = wh + 278528;
    __half* wh_c1   = wh + 294912;

    const size_t KVN = (size_t)BB*2*CC*PP;
    const int NB = (PP + 127)/128;   // 25

    const int SM128 = 2*(128*72 + 64*136)*2;
    const int SM64  = 2*( 64*72 + 64*136)*2;
    cudaFuncSetAttribute(hgemm<128, EPI_BIAS_H>, cudaFuncAttributeMaxDynamicSharedMemorySize, SM128);
    cudaFuncSetAttribute(hgemm<128, EPI_BN_H>,   cudaFuncAttributeMaxDynamicSharedMemorySize, SM128);
    cudaFuncSetAttribute(hgemm<128, EPI_PAD>,    cudaFuncAttributeMaxDynamicSharedMemorySize, SM128);
    cudaFuncSetAttribute(hgemm<64,  EPI_BNLR_H>, cudaFuncAttributeMaxDynamicSharedMemorySize, SM64);

    // 1: weight prep
    prep_kernel<<<576, 256>>>(lk_w, lv_w, gk_w, gv_w, la_w1, la_w2, c1_w,
                              lk_b, gk_b, wh, sb);
    // 2: convert inputs
    cvt_pair<<<(NXE/4 + 255)/256, 256>>>(x_s, x_fq, xH);
    // 3: border fill
    border_fill_kernel<<<(BB*CC*228 + 255)/256, 256>>>(out, c1_b);
    // 4: fused dual KV GEMM  <-- profiled
    {   dim3 g(NB, 4, 2*BB);
        hgemm<128, EPI_BIAS_H><<<g, 128, SM128>>>(wh_kvs, xH, kv, CC, 512,
                                                  sb, sb, sb,
                                                  131072, (size_t)NXE, KVN, 512);
    }
    // 5: t1
    {   dim3 g(NB, 1, BB);
        hgemm<64, EPI_BNLR_H><<<g, 128, SM64>>>(wh_la1, xH, t1H, CC, ICC,
                                                la_b1, la_g1, la_be1, 0, 0, 0, 0);
    }
    // 6: l_q
    {   dim3 g(NB, CC/128, BB);
        hgemm<128, EPI_BN_H><<<g, 128, SM128>>>(wh_la2, t1H, lqh, ICC, CC,
                                                la_b2, la_g2, la_be2, 0, 0, 0, 0);
    }
    // 7: mean
    mean_kernel<<<BB*CC, 256>>>(x_mt, xbar);
    // 8: gq MLP
    gq_kernel<<<BB, 256>>>(xbar, c11_w, c11_b, ga_w1, ga_b1, ga_g1, ga_be1,
                           ga_w2, ga_b2, ga_g2, ga_be2, gqs);
    // 9: attention
    attn_tc<<<BB*CC, 128>>>(lqh, kv, kv + KVN, gqs, fH);
    // 10: padded output conv
    {   dim3 g(NB, CC/128, BB);
        hgemm<128, EPI_PAD><<<g, 128, SM128>>>(wh_c1, fH, out, CC, CC,
                                               c1_b, c1_b, c1_b, 0, 0, 0, 0);
    }
}

// round 14
// speedup vs baseline: 1.0209x; 1.0209x over previous
#include <cuda_runtime.h>
#include <cuda_fp16.h>
#include <math.h>
#include <stdint.h>

#define BB   16
#define CC   256
#define ICC  64
#define HH   56
#define PP   (HH*HH)
#define OUTH 58
#define EPSV 1e-5f
#define SCALEV (1.0f/896.0f)

#define NXE (BB*CC*PP)

// ---------------- scratch ----------------
__device__ __half g_xH [2*NXE];
__device__ __half g_t1H[BB*ICC*PP];
__device__ __half g_lqh[BB*CC*PP];
__device__ __half g_kv [2*BB*2*CC*PP];
__device__ __half g_fH [BB*CC*PP];
__device__ float  g_xbar[BB*CC];
__device__ float  g_gqs [BB*CC];
__device__ __half g_wh  [2*512*256 + 2*64*256 + 256*256];
__device__ float  g_sb  [1024];

#define EPI_PAD    4
#define EPI_BIAS_H 5
#define EPI_BN_H   6
#define EPI_BNLR_H 7

__device__ __forceinline__ uint32_t smem_u32(const void* p){
    uint32_t a;
    asm("{ .reg .u64 t; cvta.to.shared.u64 t, %1; cvt.u32.u64 %0, t; }":"=r"(a):"l"(p));
    return a;
}
__device__ __forceinline__ void mma16(float c[4],
    uint32_t a0, uint32_t a1, uint32_t a2, uint32_t a3, uint32_t b0, uint32_t b1){
    asm volatile(
        "mma.sync.aligned.m16n8k16.row.col.f32.f16.f16.f32 "
        "{%0,%1,%2,%3}, {%4,%5,%6,%7}, {%8,%9}, {%0,%1,%2,%3};"
        : "+f"(c[0]),"+f"(c[1]),"+f"(c[2]),"+f"(c[3])
        : "r"(a0),"r"(a1),"r"(a2),"r"(a3),"r"(b0),"r"(b1));
}
__device__ __forceinline__ void ldsm4(uint32_t& r0, uint32_t& r1, uint32_t& r2, uint32_t& r3,
                                      uint32_t addr){
    asm volatile("ldmatrix.sync.aligned.m8n8.x4.shared.b16 {%0,%1,%2,%3}, [%4];"
        : "=r"(r0),"=r"(r1),"=r"(r2),"=r"(r3) : "r"(addr));
}
__device__ __forceinline__ void ldsm4t(uint32_t& r0, uint32_t& r1, uint32_t& r2, uint32_t& r3,
                                       uint32_t addr){
    asm volatile("ldmatrix.sync.aligned.m8n8.x4.trans.shared.b16 {%0,%1,%2,%3}, [%4];"
        : "=r"(r0),"=r"(r1),"=r"(r2),"=r"(r3) : "r"(addr));
}

// ================= fp16 tensor-core batched GEMM =================
// 128 threads, warp tile 64x64 (BM=128) / 64x32 (BM=64). BK=64, dynamic smem.
template<int BM, int EPI>
__global__ __launch_bounds__(128)
void hgemm(const __half* __restrict__ W, const __half* __restrict__ X,
           void* __restrict__ Yv, int K, int Mtot,
           const float* __restrict__ bias,
           const float* __restrict__ gamma,
           const float* __restrict__ beta,
           size_t wstride, size_t xstride, size_t ystride, int bstride)
{
    constexpr int BN = 128, BK = 64;
    constexpr int WM = (BM == 128) ? 2 : 1;
    constexpr int WN = 4 / WM;
    constexpr int MT = 4;
    constexpr int NT = BN / (WN * 8);
    constexpr int ASTR = 72;
    constexpr int BSTR = 136;
    constexpr int ASZ = BM * ASTR;
    constexpr int BSZ = BK * BSTR;

    extern __shared__ __align__(16) __half dsm[];
    __half* sA = dsm;
    __half* sB = dsm + 2*ASZ;

    const int tid = threadIdx.x, wid = tid >> 5, lane = tid & 31;
    const int gid = lane >> 2, tig = lane & 3;
    const int l8 = lane & 7, lb1 = (lane >> 3) & 1, lb2 = lane >> 4;
    const int warpM = wid / WN, warpN = wid - warpM * WN;
    const int m0 = blockIdx.y * BM, n0 = blockIdx.x * BN;
    const int which = blockIdx.z / BB;
    const int b = blockIdx.z - which * BB;

    const __half* Wt = W + which*wstride + (size_t)m0 * K;
    const __half* Xb = X + which*xstride + (size_t)b * K * PP;
    const float* biasW = bias + which * bstride;
    const uint32_t sAb = smem_u32(sA);
    const uint32_t sBb = smem_u32(sB);

    float c[MT][NT][4];
    #pragma unroll
    for(int m=0;m<MT;m++)
        #pragma unroll
        for(int n=0;n<NT;n++)
            #pragma unroll
            for(int q=0;q<4;q++) c[m][n][q]=0.f;

    const int NK = K >> 6;

    auto load_tile = [&](int kt, int s){
        #pragma unroll
        for(int i = tid; i < BM*8; i += 128){
            int m = i >> 3, k8 = (i & 7) << 3;
            uint32_t dst = sAb + (s*ASZ + m*ASTR + k8) * 2;
            asm volatile("cp.async.cg.shared.global [%0], [%1], 16;"
                :: "r"(dst), "l"(Wt + (size_t)m*K + kt*64 + k8));
        }
        #pragma unroll
        for(int i = tid; i < 1024; i += 128){
            int kr = i >> 4, c8 = (i & 15) << 3;
            int p = n0 + c8;
            const __half* src = (p < PP) ? (Xb + (size_t)(kt*64 + kr)*PP + p) : Xb;
            uint32_t sz = (p < PP) ? 16u : 0u;
            uint32_t dst = sBb + (s*BSZ + kr*BSTR + c8) * 2;
            asm volatile("cp.async.cg.shared.global [%0], [%1], 16, %2;"
                :: "r"(dst), "l"(src), "r"(sz));
        }
        asm volatile("cp.async.commit_group;" ::: "memory");
    };

    load_tile(0, 0);

    for(int kt = 0; kt < NK; kt++){
        const int s = kt & 1;
        if(kt + 1 < NK){
            load_tile(kt + 1, 1 - s);
            asm volatile("cp.async.wait_group 1;" ::: "memory");
        } else {
            asm volatile("cp.async.wait_group 0;" ::: "memory");
        }
        __syncthreads();

        const uint32_t aBase = sAb + s*ASZ*2;
        const uint32_t bBase = sBb + s*BSZ*2;
        #pragma unroll
        for(int kk = 0; kk < BK; kk += 16){
            uint32_t a[MT][4], bb[NT][2];
            #pragma unroll
            for(int m=0;m<MT;m++){
                int mr = warpM*64 + m*16;
                uint32_t addr = aBase + (uint32_t)(((mr + l8 + lb1*8)*ASTR + kk + lb2*8)*2);
                ldsm4(a[m][0],a[m][1],a[m][2],a[m][3], addr);
            }
            #pragma unroll
            for(int np=0; np<NT/2; np++){
                int nc = warpN*(NT*8) + np*16;
                uint32_t addr = bBase + (uint32_t)(((kk + lb1*8 + l8)*BSTR + nc + lb2*8)*2);
                ldsm4t(bb[2*np][0], bb[2*np][1], bb[2*np+1][0], bb[2*np+1][1], addr);
            }
            #pragma unroll
            for(int m=0;m<MT;m++)
                #pragma unroll
                for(int n=0;n<NT;n++)
                    mma16(c[m][n], a[m][0],a[m][1],a[m][2],a[m][3], bb[n][0],bb[n][1]);
        }
        __syncthreads();
    }

    const float rs = rsqrtf(1.0f + EPSV);
    #pragma unroll
    for(int m=0;m<MT;m++){
        #pragma unroll
        for(int half_=0; half_<2; half_++){
            const int row = m0 + warpM*64 + m*16 + gid + half_*8;
            float add0=0.f, sc=1.f, sh=0.f;
            if(EPI==EPI_BIAS_H || EPI==EPI_PAD) add0=biasW[row];
            if(EPI==EPI_BN_H || EPI==EPI_BNLR_H){
                add0=biasW[row]; sc=gamma[row]*rs; sh=beta[row];
            }
            #pragma unroll
            for(int n=0;n<NT;n++){
                const int p = n0 + warpN*(NT*8) + n*8 + 2*tig;
                if(p < PP){
                    float y0 = c[m][n][half_*2+0];
                    float y1 = c[m][n][half_*2+1];
                    if(EPI==EPI_PAD){
                        float* Y = (float*)Yv;
                        y0 += add0; y1 += add0;
                        int h=p/HH, w=p-h*HH;
                        float* yb = Y + ((size_t)(b*CC+row)*OUTH)*OUTH;
                        yb[(h+1)*OUTH + w+1] = y0;
                        int p1=p+1, h1=p1/HH, w1=p1-h1*HH;
                        yb[(h1+1)*OUTH + w1+1] = y1;
                    } else {
                        if(EPI==EPI_BIAS_H){ y0+=add0; y1+=add0; }
                        if(EPI==EPI_BN_H){ y0=(y0+add0)*sc+sh; y1=(y1+add0)*sc+sh; }
                        if(EPI==EPI_BNLR_H){
                            y0=(y0+add0)*sc+sh; y0=(y0>=0.f)?y0:0.2f*y0;
                            y1=(y1+add0)*sc+sh; y1=(y1>=0.f)?y1:0.2f*y1;
                        }
                        __half* Yh = (__half*)Yv + which*ystride;
                        *reinterpret_cast<__half2*>(Yh + ((size_t)b*Mtot + row)*PP + p)
                            = __floats2half2_rn(y0, y1);
                    }
                }
            }
        }
    }
}

// ================= tensor-core attention =================
__global__ __launch_bounds__(128)
void attn_tc(const __half* __restrict__ lqh, const __half* __restrict__ kvsh,
             const __half* __restrict__ kvfqh, const float* __restrict__ gqs,
             __half* __restrict__ fH)
{
    constexpr int STR = 72;
    __shared__ __align__(16) __half sm[5*64*STR];
    __half* sQ  = sm;
    __half* sK  = sm + 1*64*STR;
    __half* sGK = sm + 2*64*STR;
    __half* sV  = sm + 3*64*STR;
    __half* sGV = sm + 4*64*STR;

    const int bc = blockIdx.x;
    const int b = bc >> 8, ch = bc & 255;
    const size_t base_q = (size_t)bc * PP;
    const size_t base_k = ((size_t)(b*512 + ch)) * PP;
    const size_t base_v = base_k + (size_t)256 * PP;
    const int tid = threadIdx.x, wid = tid>>5, lane = tid&31;
    const int gid = lane>>2, tig = lane&3;
    const int l8 = lane&7, lb1 = (lane>>3)&1, lb2 = lane>>4;

    const __half* srcs[5] = { lqh + base_q, kvsh + base_k, kvfqh + base_k,
                              kvsh + base_v, kvfqh + base_v };
    uint32_t* usm = (uint32_t*)sm;

    for(int i = tid; i < 5*64*4; i += 128){
        int arr = i >> 8, rem = i & 255;
        int r = rem >> 2, j = rem & 3;
        usm[arr*64*36 + r*36 + 28 + j] = 0;
    }
    for(int i = tid; i < 5*8*28; i += 128){
        int arr = i / 224, rem = i - arr*224;
        int r = 56 + rem/28, j = rem - (rem/28)*28;
        usm[arr*64*36 + r*36 + j] = 0;
    }
    const uint32_t smB = smem_u32(sm);
    #pragma unroll
    for(int arr = 0; arr < 5; arr++){
        for(int i = tid; i < 56*7; i += 128){
            int r = i/7, chx = i - r*7;
            uint32_t dst = smB + (arr*64*STR + r*STR + chx*8)*2;
            asm volatile("cp.async.cg.shared.global [%0], [%1], 16;"
                :: "r"(dst), "l"(srcs[arr] + (size_t)r*HH + chx*8));
        }
    }
    asm volatile("cp.async.commit_group;" ::: "memory");
    asm volatile("cp.async.wait_group 0;" ::: "memory");
    __syncthreads();

    const uint32_t qB = smem_u32(sQ), kB = smem_u32(sK), vB = smem_u32(sV);
    const uint32_t gkB = smem_u32(sGK), gvB = smem_u32(sGV);
    const int m0 = wid*16;
    const uint32_t aOff = (uint32_t)(((m0 + l8 + lb1*8)*STR)*2);
    const uint32_t bRowN = (uint32_t)((l8 + lb2*8)*STR*2);

    // ---- S = Q @ K^T ----
    float c[8][4];
    #pragma unroll
    for(int n=0;n<8;n++){ c[n][0]=0; c[n][1]=0; c[n][2]=0; c[n][3]=0; }
    #pragma unroll
    for(int kk = 0; kk < 64; kk += 16){
        uint32_t a0,a1,a2,a3;
        ldsm4(a0,a1,a2,a3, qB + aOff + (kk + lb2*8)*2);
        uint32_t bb[8][2];
        #pragma unroll
        for(int np=0;np<4;np++){
            uint32_t addr = kB + bRowN + (uint32_t)((np*16*STR + kk + lb1*8)*2);
            ldsm4(bb[2*np][0], bb[2*np][1], bb[2*np+1][0], bb[2*np+1][1], addr);
        }
        #pragma unroll
        for(int n=0;n<8;n++)
            mma16(c[n], a0,a1,a2,a3, bb[n][0], bb[n][1]);
    }

    // ---- local softmax (quad shuffles), P -> sQ (warp-private rows) ----
    #pragma unroll
    for(int half_=0; half_<2; half_++){
        const int h2 = half_*2;
        float m = -1e30f;
        #pragma unroll
        for(int n=0;n<7;n++) m = fmaxf(m, fmaxf(c[n][h2], c[n][h2+1]));
        m = fmaxf(m, __shfl_xor_sync(0xffffffffu, m, 1));
        m = fmaxf(m, __shfl_xor_sync(0xffffffffu, m, 2));
        float s = 0.f;
        #pragma unroll
        for(int n=0;n<7;n++){
            float e0 = __expf((c[n][h2  ] - m)*SCALEV);
            float e1 = __expf((c[n][h2+1] - m)*SCALEV);
            c[n][h2]=e0; c[n][h2+1]=e1; s += e0+e1;
        }
        s += __shfl_xor_sync(0xffffffffu, s, 1);
        s += __shfl_xor_sync(0xffffffffu, s, 2);
        const float inv = 1.f/s;
        const int row = m0 + gid + half_*8;
        #pragma unroll
        for(int n=0;n<8;n++){
            __half2 hv = (n<7) ? __floats2half2_rn(c[n][h2]*inv, c[n][h2+1]*inv)
                               : __floats2half2_rn(0.f, 0.f);
            *reinterpret_cast<__half2*>(sQ + row*STR + n*8 + 2*tig) = hv;
        }
    }

    // ---- global softmax: parallel, warp-private rows of sGK ----
    {
        const float gq = gqs[bc];
        #pragma unroll
        for(int half_=0; half_<2; half_++){
            const int row = m0 + gid + half_*8;
            float v[7][2];
            float m = -1e30f;
            #pragma unroll
            for(int n=0;n<7;n++){
                __half2 hv = *reinterpret_cast<__half2*>(sGK + row*STR + n*8 + 2*tig);
                v[n][0] = gq*__low2float(hv);
                v[n][1] = gq*__high2float(hv);
                m = fmaxf(m, fmaxf(v[n][0], v[n][1]));
            }
            m = fmaxf(m, __shfl_xor_sync(0xffffffffu, m, 1));
            m = fmaxf(m, __shfl_xor_sync(0xffffffffu, m, 2));
            float s = 0.f;
            #pragma unroll
            for(int n=0;n<7;n++){
                v[n][0]=__expf(v[n][0]-m); v[n][1]=__expf(v[n][1]-m);
                s += v[n][0]+v[n][1];
            }
            s += __shfl_xor_sync(0xffffffffu, s, 1);
            s += __shfl_xor_sync(0xffffffffu, s, 2);
            const float inv = 1.f/s;
            #pragma unroll
            for(int n=0;n<8;n++){
                __half2 hv = (n<7) ? __floats2half2_rn(v[n][0]*inv, v[n][1]*inv)
                                   : __floats2half2_rn(0.f, 0.f);
                *reinterpret_cast<__half2*>(sGK + row*STR + n*8 + 2*tig) = hv;
            }
        }
    }
    __syncwarp();

    // ---- O = P@V^T + GS@GV^T ----
    #pragma unroll
    for(int n=0;n<8;n++){ c[n][0]=0; c[n][1]=0; c[n][2]=0; c[n][3]=0; }
    #pragma unroll
    for(int kk = 0; kk < 64; kk += 16){
        uint32_t a0,a1,a2,a3;
        ldsm4(a0,a1,a2,a3, qB + aOff + (kk + lb2*8)*2);
        uint32_t bb[8][2];
        #pragma unroll
        for(int np=0;np<4;np++){
            int nc = np*16;
            uint32_t addr = vB + (uint32_t)(((kk + lb1*8 + l8)*STR + nc + lb2*8)*2);
            ldsm4t(bb[2*np][0], bb[2*np][1], bb[2*np+1][0], bb[2*np+1][1], addr);
        }
        #pragma unroll
        for(int n=0;n<8;n++)
            mma16(c[n], a0,a1,a2,a3, bb[n][0], bb[n][1]);
    }
    #pragma unroll
    for(int kk = 0; kk < 64; kk += 16){
        uint32_t a0,a1,a2,a3;
        ldsm4(a0,a1,a2,a3, gkB + aOff + (kk + lb2*8)*2);
        uint32_t bb[8][2];
        #pragma unroll
        for(int np=0;np<4;np++){
            int nc = np*16;
            uint32_t addr = gvB + (uint32_t)(((kk + lb1*8 + l8)*STR + nc + lb2*8)*2);
            ldsm4t(bb[2*np][0], bb[2*np][1], bb[2*np+1][0], bb[2*np+1][1], addr);
        }
        #pragma unroll
        for(int n=0;n<8;n++)
            mma16(c[n], a0,a1,a2,a3, bb[n][0], bb[n][1]);
    }

    #pragma unroll
    for(int half_=0; half_<2; half_++){
        const int row = m0 + gid + half_*8;
        if(row < 56){
            #pragma unroll
            for(int n=0;n<7;n++){
                *reinterpret_cast<__half2*>(fH + base_q + row*HH + n*8 + 2*tig)
                    = __floats2half2_rn(c[n][half_*2], c[n][half_*2+1]);
            }
        }
    }
}

// ================= merged setup: cvt + weight prep + border fill + mean =================
#define NCVT  12544            // NXE/4/256
#define NPREP 576
#define NBORD 3648             // ceil(16*256*228/256)
#define NMEAN 4096

__global__ void setup_kernel(const float* __restrict__ x_s, const float* __restrict__ x_fq,
                             const float* __restrict__ x_mt,
                             const float* __restrict__ lk_w, const float* __restrict__ lv_w,
                             const float* __restrict__ gk_w, const float* __restrict__ gv_w,
                             const float* __restrict__ la_w1, const float* __restrict__ la_w2,
                             const float* __restrict__ c1_w,
                             const float* __restrict__ lk_b, const float* __restrict__ gk_b,
                             const float* __restrict__ c1_b,
                             __half* __restrict__ xH, __half* __restrict__ wh,
                             float* __restrict__ sb, float* __restrict__ out,
                             float* __restrict__ xbar)
{
    __shared__ float red[256];
    const int blk = blockIdx.x, tid = threadIdx.x;

    if(blk < NCVT){
        const int idx = blk*256 + tid;
        float4 v = reinterpret_cast<const float4*>(x_s)[idx];
        __half2 h0 = __floats2half2_rn(v.x, v.y);
        __half2 h1 = __floats2half2_rn(v.z, v.w);
        uint2 o;
        o.x = *reinterpret_cast<uint32_t*>(&h0);
        o.y = *reinterpret_cast<uint32_t*>(&h1);
        reinterpret_cast<uint2*>(xH)[idx] = o;
        float4 w = reinterpret_cast<const float4*>(x_fq)[idx];
        __half2 g0 = __floats2half2_rn(w.x, w.y);
        __half2 g1 = __floats2half2_rn(w.z, w.w);
        uint2 o2;
        o2.x = *reinterpret_cast<uint32_t*>(&g0);
        o2.y = *reinterpret_cast<uint32_t*>(&g1);
        reinterpret_cast<uint2*>(xH + NXE)[idx] = o2;
    } else if(blk < NCVT + NPREP){
        const int i = (blk - NCVT)*256 + tid;
        if(i < 131072){
            wh[i]          = __float2half(i < 65536 ? lk_w[i] : lv_w[i-65536]);
            wh[131072 + i] = __float2half(i < 65536 ? gk_w[i] : gv_w[i-65536]);
        } else if(i < 147456){
            int j = i - 131072;
            wh[262144 + j] = __float2half(la_w1[j]);
            wh[278528 + j] = __float2half(la_w2[j]);
        }
        if(i < 65536) wh[294912 + i] = __float2half(c1_w[i]);
        if(i < 512){
            sb[i]       = (i < 256) ? lk_b[i] : 0.f;
            sb[512 + i] = (i < 256) ? gk_b[i] : 0.f;
        }
    } else if(blk < NCVT + NPREP + NBORD){
        const int idx = (blk - NCVT - NPREP)*256 + tid;
        const int total = BB*CC*228;
        if(idx < total){
            const int bc = idx / 228, j = idx - bc*228;
            int h, w;
            if(j < 58){ h = 0; w = j; }
            else if(j < 116){ h = 57; w = j - 58; }
            else { int j2 = j - 116; h = 1 + (j2 >> 1); w = (j2 & 1) * 57; }
            out[((size_t)bc*OUTH + h)*OUTH + w] = c1_b[bc & 255];
        }
    } else {
        const int bc = blk - NCVT - NPREP - NBORD;
        const float* p = x_mt + (size_t)bc*PP;
        float s = 0.f;
        for(int i = tid; i < PP; i += 256) s += p[i];
        red[tid] = s; __syncthreads();
        for(int o = 128; o > 0; o >>= 1){
            if(tid < o) red[tid] += red[tid + o];
            __syncthreads();
        }
        if(tid == 0) xbar[bc] = red[0]*(1.0f/PP);
    }
}

// ---------------- global-branch query MLP ----------------
__global__ void gq_kernel(const float* __restrict__ xbar,
                          const float* __restrict__ c11_w, const float* __restrict__ c11_b,
                          const float* __restrict__ ga_w1, const float* __restrict__ ga_b1,
                          const float* __restrict__ ga_g1, const float* __restrict__ ga_be1,
                          const float* __restrict__ ga_w2, const float* __restrict__ ga_b2,
                          const float* __restrict__ ga_g2, const float* __restrict__ ga_be2,
                          float* __restrict__ gqs)
{
    __shared__ float xb[CC], pv[CC], tv[ICC];
    const int b=blockIdx.x, t=threadIdx.x;
    const float rs=rsqrtf(1.0f+EPSV);
    xb[t]=xbar[b*CC+t]; __syncthreads();
    { float d=0.f; const float* wr=c11_w+(size_t)t*CC;
      for(int c=0;c<CC;c++) d=fmaf(wr[c],xb[c],d);
      pv[t]=d+c11_b[t]; }
    __syncthreads();
    if(t<ICC){ float d=0.f; const float* wr=ga_w1+(size_t)t*CC;
      for(int c=0;c<CC;c++) d=fmaf(wr[c],pv[c],d);
      d=(d+ga_b1[t])*(ga_g1[t]*rs)+ga_be1[t];
      tv[t]=(d>=0.f)?d:0.2f*d; }
    __syncthreads();
    { float d=0.f; const float* wr=ga_w2+(size_t)t*ICC;
      for(int i=0;i<ICC;i++) d=fmaf(wr[i],tv[i],d);
      d=(d+ga_b2[t])*(ga_g2[t]*rs)+ga_be2[t];
      gqs[b*CC+t]=d*SCALEV; }
}

// ---------------- launch ----------------
extern "C" void kernel_launch(void* const* d_in, const int* in_sizes, int n_in,
                              void* d_out, int out_size)
{
    const float* x_s  =(const float*)d_in[0];
    const float* x_fq =(const float*)d_in[1];
    const float* x_mt =(const float*)d_in[2];
    const float* la_w1=(const float*)d_in[3];
    const float* la_b1=(const float*)d_in[4];
    const float* la_g1=(const float*)d_in[5];
    const float* la_be1=(const float*)d_in[6];
    const float* la_w2=(const float*)d_in[7];
    const float* la_b2=(const float*)d_in[8];
    const float* la_g2=(const float*)d_in[9];
    const float* la_be2=(const float*)d_in[10];
    const float* lk_w =(const float*)d_in[11];
    const float* lk_b =(const float*)d_in[12];
    const float* lv_w =(const float*)d_in[13];
    const float* ga_w1=(const float*)d_in[14];
    const float* ga_b1=(const float*)d_in[15];
    const float* ga_g1=(const float*)d_in[16];
    const float* ga_be1=(const float*)d_in[17];
    const float* ga_w2=(const float*)d_in[18];
    const float* ga_b2=(const float*)d_in[19];
    const float* ga_g2=(const float*)d_in[20];
    const float* ga_be2=(const float*)d_in[21];
    const float* gk_w =(const float*)d_in[22];
    const float* gk_b =(const float*)d_in[23];
    const float* gv_w =(const float*)d_in[24];
    const float* c11_w=(const float*)d_in[25];
    const float* c11_b=(const float*)d_in[26];
    const float* c1_w =(const float*)d_in[27];
    const float* c1_b =(const float*)d_in[28];
    float* out=(float*)d_out;

    __half *xH,*t1H,*lqh,*kv,*fH,*wh;
    float *xbar,*gqs,*sb;
    cudaGetSymbolAddress((void**)&xH,  g_xH);
    cudaGetSymbolAddress((void**)&t1H, g_t1H);
    cudaGetSymbolAddress((void**)&lqh, g_lqh);
    cudaGetSymbolAddress((void**)&kv,  g_kv);
    cudaGetSymbolAddress((void**)&fH,  g_fH);
    cudaGetSymbolAddress((void**)&xbar,g_xbar);
    cudaGetSymbolAddress((void**)&gqs, g_gqs);
    cudaGetSymbolAddress((void**)&wh,  g_wh);
    cudaGetSymbolAddress((void**)&sb,  g_sb);

    __half* wh_kvs  = wh;
    __half* wh_la1  = wh + 262144;
    __half* wh_la2  = wh + 278528;
    __half* wh_c1   = wh + 294912;

    const size_t KVN = (size_t)BB*2*CC*PP;
    const int NB = (PP + 127)/128;   // 25

    const int SM128 = 2*(128*72 + 64*136)*2;
    const int SM64  = 2*( 64*72 + 64*136)*2;
    cudaFuncSetAttribute(hgemm<128, EPI_BIAS_H>, cudaFuncAttributeMaxDynamicSharedMemorySize, SM128);
    cudaFuncSetAttribute(hgemm<128, EPI_BN_H>,   cudaFuncAttributeMaxDynamicSharedMemorySize, SM128);
    cudaFuncSetAttribute(hgemm<128, EPI_PAD>,    cudaFuncAttributeMaxDynamicSharedMemorySize, SM128);
    cudaFuncSetAttribute(hgemm<64,  EPI_BNLR_H>, cudaFuncAttributeMaxDynamicSharedMemorySize, SM64);

    // 1: merged setup (cvt + prep + border + mean)
    setup_kernel<<<NCVT + NPREP + NBORD + NMEAN, 256>>>(
        x_s, x_fq, x_mt, lk_w, lv_w, gk_w, gv_w, la_w1, la_w2, c1_w,
        lk_b, gk_b, c1_b, xH, wh, sb, out, xbar);
    // 2: gq MLP
    gq_kernel<<<BB, 256>>>(xbar, c11_w, c11_b, ga_w1, ga_b1, ga_g1, ga_be1,
                           ga_w2, ga_b2, ga_g2, ga_be2, gqs);
    // 3: t1
    {   dim3 g(NB, 1, BB);
        hgemm<64, EPI_BNLR_H><<<g, 128, SM64>>>(wh_la1, xH, t1H, CC, ICC,
                                                la_b1, la_g1, la_be1, 0, 0, 0, 0);
    }
    // 4: fused dual KV GEMM  <-- profiled
    {   dim3 g(NB, 4, 2*BB);
        hgemm<128, EPI_BIAS_H><<<g, 128, SM128>>>(wh_kvs, xH, kv, CC, 512,
                                                  sb, sb, sb,
                                                  131072, (size_t)NXE, KVN, 512);
    }
    // 5: l_q
    {   dim3 g(NB, CC/128, BB);
        hgemm<128, EPI_BN_H><<<g, 128, SM128>>>(wh_la2, t1H, lqh, ICC, CC,
                                                la_b2, la_g2, la_be2, 0, 0, 0, 0);
    }
    // 6: attention
    attn_tc<<<BB*CC, 128>>>(lqh, kv, kv + KVN, gqs, fH);
    // 7: padded output conv
    {   dim3 g(NB, CC/128, BB);
        hgemm<128, EPI_PAD><<<g, 128, SM128>>>(wh_c1, fH, out, CC, CC,
                                               c1_b, c1_b, c1_b, 0, 0, 0, 0);
    }
}

// round 15
// speedup vs baseline: 1.1829x; 1.1587x over previous
#include <cuda_runtime.h>
#include <cuda_fp16.h>
#include <math.h>
#include <stdint.h>

#define BB   16
#define CC   256
#define ICC  64
#define HH   56
#define PP   (HH*HH)
#define OUTH 58
#define EPSV 1e-5f
#define SCALEV (1.0f/896.0f)

#define NXE (BB*CC*PP)
#define KVN ((size_t)BB*2*CC*PP)

// wh layout (halfs): kv_s[0:131072) kv_fq[131072:262144) la1p[262144:294912)
//                    la2[294912:311296) c1[311296:376832)
__device__ __half g_xH [2*NXE];
__device__ __half g_t1H[BB*ICC*PP];
__device__ __half g_lqh[BB*CC*PP];
__device__ __half g_kv [2*BB*2*CC*PP];
__device__ __half g_fH [BB*CC*PP];
__device__ float  g_xbar[BB*CC];
__device__ float  g_gqs [BB*CC];
__device__ __half g_wh  [376832];
__device__ float  g_sb  [1024];

#define EPI_PAD    4
#define EPI_BN_H   6

__device__ __forceinline__ uint32_t smem_u32(const void* p){
    uint32_t a;
    asm("{ .reg .u64 t; cvta.to.shared.u64 t, %1; cvt.u32.u64 %0, t; }":"=r"(a):"l"(p));
    return a;
}
__device__ __forceinline__ void mma16(float c[4],
    uint32_t a0, uint32_t a1, uint32_t a2, uint32_t a3, uint32_t b0, uint32_t b1){
    asm volatile(
        "mma.sync.aligned.m16n8k16.row.col.f32.f16.f16.f32 "
        "{%0,%1,%2,%3}, {%4,%5,%6,%7}, {%8,%9}, {%0,%1,%2,%3};"
        : "+f"(c[0]),"+f"(c[1]),"+f"(c[2]),"+f"(c[3])
        : "r"(a0),"r"(a1),"r"(a2),"r"(a3),"r"(b0),"r"(b1));
}
__device__ __forceinline__ void ldsm4(uint32_t& r0, uint32_t& r1, uint32_t& r2, uint32_t& r3,
                                      uint32_t addr){
    asm volatile("ldmatrix.sync.aligned.m8n8.x4.shared.b16 {%0,%1,%2,%3}, [%4];"
        : "=r"(r0),"=r"(r1),"=r"(r2),"=r"(r3) : "r"(addr));
}
__device__ __forceinline__ void ldsm4t(uint32_t& r0, uint32_t& r1, uint32_t& r2, uint32_t& r3,
                                       uint32_t addr){
    asm volatile("ldmatrix.sync.aligned.m8n8.x4.trans.shared.b16 {%0,%1,%2,%3}, [%4];"
        : "=r"(r0),"=r"(r1),"=r"(r2),"=r"(r3) : "r"(addr));
}

// ================= mega kernel: KV GEMM (y<4) + t1 GEMM (y==4) + gq MLP (y==5) =================
// GEMM: 128 thr, tile 128x128, BK=64, double-buffered cp.async.
__global__ __launch_bounds__(128)
void mega_kernel(const float* __restrict__ la_b1, const float* __restrict__ la_g1,
                 const float* __restrict__ la_be1,
                 const float* __restrict__ c11_w, const float* __restrict__ c11_b,
                 const float* __restrict__ ga_w1, const float* __restrict__ ga_b1,
                 const float* __restrict__ ga_g1, const float* __restrict__ ga_be1,
                 const float* __restrict__ ga_w2, const float* __restrict__ ga_b2,
                 const float* __restrict__ ga_g2, const float* __restrict__ ga_be2)
{
    constexpr int BM = 128, BK = 64;
    constexpr int MT = 4, NT = 8;
    constexpr int ASTR = 72, BSTR = 136;
    constexpr int ASZ = BM * ASTR;
    constexpr int BSZ = BK * BSTR;

    extern __shared__ __align__(16) __half dsm[];

    const float rs = rsqrtf(1.0f + EPSV);
    const int tid = threadIdx.x;

    // ---- gq mode ----
    if(blockIdx.y == 5){
        if(blockIdx.x >= 16 || blockIdx.z > 0) return;
        float* fs = (float*)dsm;
        float* xb = fs; float* pv = fs + 256; float* tv = fs + 512;
        const int b = blockIdx.x;
        xb[tid]     = g_xbar[b*CC + tid];
        xb[tid+128] = g_xbar[b*CC + tid + 128];
        __syncthreads();
        for(int cc = tid; cc < 256; cc += 128){
            float d = 0.f; const float* wr = c11_w + (size_t)cc*CC;
            for(int c = 0; c < CC; c++) d = fmaf(wr[c], xb[c], d);
            pv[cc] = d + c11_b[cc];
        }
        __syncthreads();
        if(tid < ICC){
            float d = 0.f; const float* wr = ga_w1 + (size_t)tid*CC;
            for(int c = 0; c < CC; c++) d = fmaf(wr[c], pv[c], d);
            d = (d + ga_b1[tid])*(ga_g1[tid]*rs) + ga_be1[tid];
            tv[tid] = (d >= 0.f) ? d : 0.2f*d;
        }
        __syncthreads();
        for(int cc = tid; cc < 256; cc += 128){
            float d = 0.f; const float* wr = ga_w2 + (size_t)cc*ICC;
            for(int i = 0; i < ICC; i++) d = fmaf(wr[i], tv[i], d);
            d = (d + ga_b2[cc])*(ga_g2[cc]*rs) + ga_be2[cc];
            g_gqs[b*CC + cc] = d*SCALEV;
        }
        return;
    }

    const bool t1m = (blockIdx.y == 4);
    if(t1m && blockIdx.z >= BB) return;

    __half* sA = dsm;
    __half* sB = dsm + 2*ASZ;
    const int wid = tid >> 5, lane = tid & 31;
    const int gid = lane >> 2, tig = lane & 3;
    const int l8 = lane & 7, lb1 = (lane >> 3) & 1, lb2 = lane >> 4;
    const int warpM = wid >> 1, warpN = wid & 1;
    const int n0 = blockIdx.x * 128;
    const int m0 = t1m ? 0 : blockIdx.y * BM;
    const int which = t1m ? 0 : (blockIdx.z / BB);
    const int b = t1m ? blockIdx.z : (blockIdx.z - which * BB);
    const int K = CC;

    const __half* Wt = t1m ? (g_wh + 262144)
                           : (g_wh + which*131072 + (size_t)m0 * K);
    const __half* Xb = g_xH + which*(size_t)NXE + (size_t)b * K * PP;
    const uint32_t sAb = smem_u32(sA);
    const uint32_t sBb = smem_u32(sB);

    float c[MT][NT][4];
    #pragma unroll
    for(int m=0;m<MT;m++)
        #pragma unroll
        for(int n=0;n<NT;n++)
            #pragma unroll
            for(int q=0;q<4;q++) c[m][n][q]=0.f;

    const int NK = K >> 6;

    auto load_tile = [&](int kt, int s){
        #pragma unroll
        for(int i = tid; i < BM*8; i += 128){
            int m = i >> 3, k8 = (i & 7) << 3;
            uint32_t dst = sAb + (s*ASZ + m*ASTR + k8) * 2;
            asm volatile("cp.async.cg.shared.global [%0], [%1], 16;"
                :: "r"(dst), "l"(Wt + (size_t)m*K + kt*64 + k8));
        }
        #pragma unroll
        for(int i = tid; i < 1024; i += 128){
            int kr = i >> 4, c8 = (i & 15) << 3;
            int p = n0 + c8;
            const __half* src = (p < PP) ? (Xb + (size_t)(kt*64 + kr)*PP + p) : Xb;
            uint32_t sz = (p < PP) ? 16u : 0u;
            uint32_t dst = sBb + (s*BSZ + kr*BSTR + c8) * 2;
            asm volatile("cp.async.cg.shared.global [%0], [%1], 16, %2;"
                :: "r"(dst), "l"(src), "r"(sz));
        }
        asm volatile("cp.async.commit_group;" ::: "memory");
    };

    load_tile(0, 0);

    for(int kt = 0; kt < NK; kt++){
        const int s = kt & 1;
        if(kt + 1 < NK){
            load_tile(kt + 1, 1 - s);
            asm volatile("cp.async.wait_group 1;" ::: "memory");
        } else {
            asm volatile("cp.async.wait_group 0;" ::: "memory");
        }
        __syncthreads();

        const uint32_t aBase = sAb + s*ASZ*2;
        const uint32_t bBase = sBb + s*BSZ*2;
        #pragma unroll
        for(int kk = 0; kk < BK; kk += 16){
            uint32_t a[MT][4], bb[NT][2];
            #pragma unroll
            for(int m=0;m<MT;m++){
                int mr = warpM*64 + m*16;
                uint32_t addr = aBase + (uint32_t)(((mr + l8 + lb1*8)*ASTR + kk + lb2*8)*2);
                ldsm4(a[m][0],a[m][1],a[m][2],a[m][3], addr);
            }
            #pragma unroll
            for(int np=0; np<4; np++){
                int nc = warpN*64 + np*16;
                uint32_t addr = bBase + (uint32_t)(((kk + lb1*8 + l8)*BSTR + nc + lb2*8)*2);
                ldsm4t(bb[2*np][0], bb[2*np][1], bb[2*np+1][0], bb[2*np+1][1], addr);
            }
            #pragma unroll
            for(int m=0;m<MT;m++)
                #pragma unroll
                for(int n=0;n<NT;n++)
                    mma16(c[m][n], a[m][0],a[m][1],a[m][2],a[m][3], bb[n][0],bb[n][1]);
        }
        __syncthreads();
    }

    #pragma unroll
    for(int m=0;m<MT;m++){
        #pragma unroll
        for(int half_=0; half_<2; half_++){
            const int row = warpM*64 + m*16 + gid + half_*8;
            if(t1m){
                if(row >= ICC) continue;
                float add0 = la_b1[row], sc = la_g1[row]*rs, sh = la_be1[row];
                #pragma unroll
                for(int n=0;n<NT;n++){
                    const int p = n0 + warpN*64 + n*8 + 2*tig;
                    if(p < PP){
                        float y0 = (c[m][n][half_*2+0] + add0)*sc + sh;
                        float y1 = (c[m][n][half_*2+1] + add0)*sc + sh;
                        y0 = (y0>=0.f)? y0 : 0.2f*y0;
                        y1 = (y1>=0.f)? y1 : 0.2f*y1;
                        *reinterpret_cast<__half2*>(g_t1H + ((size_t)b*ICC + row)*PP + p)
                            = __floats2half2_rn(y0, y1);
                    }
                }
            } else {
                const int grow = m0 + row;
                const float add0 = g_sb[which*512 + grow];
                #pragma unroll
                for(int n=0;n<NT;n++){
                    const int p = n0 + warpN*64 + n*8 + 2*tig;
                    if(p < PP){
                        float y0 = c[m][n][half_*2+0] + add0;
                        float y1 = c[m][n][half_*2+1] + add0;
                        *reinterpret_cast<__half2*>(
                            g_kv + which*KVN + ((size_t)b*512 + grow)*PP + p)
                            = __floats2half2_rn(y0, y1);
                    }
                }
            }
        }
    }
}

// ================= hgemm (lq, c1) =================
template<int EPI>
__global__ __launch_bounds__(128)
void hgemm(const __half* __restrict__ W, const __half* __restrict__ X,
           void* __restrict__ Yv, int K, int Mtot,
           const float* __restrict__ bias,
           const float* __restrict__ gamma,
           const float* __restrict__ beta)
{
    constexpr int BM = 128, BK = 64;
    constexpr int MT = 4, NT = 8;
    constexpr int ASTR = 72, BSTR = 136;
    constexpr int ASZ = BM * ASTR;
    constexpr int BSZ = BK * BSTR;

    extern __shared__ __align__(16) __half dsm[];
    __half* sA = dsm;
    __half* sB = dsm + 2*ASZ;

    const int tid = threadIdx.x, wid = tid >> 5, lane = tid & 31;
    const int gid = lane >> 2, tig = lane & 3;
    const int l8 = lane & 7, lb1 = (lane >> 3) & 1, lb2 = lane >> 4;
    const int warpM = wid >> 1, warpN = wid & 1;
    const int m0 = blockIdx.y * BM, n0 = blockIdx.x * 128;
    const int b = blockIdx.z;

    const __half* Wt = W + (size_t)m0 * K;
    const __half* Xb = X + (size_t)b * K * PP;
    const uint32_t sAb = smem_u32(sA);
    const uint32_t sBb = smem_u32(sB);

    float c[MT][NT][4];
    #pragma unroll
    for(int m=0;m<MT;m++)
        #pragma unroll
        for(int n=0;n<NT;n++)
            #pragma unroll
            for(int q=0;q<4;q++) c[m][n][q]=0.f;

    const int NK = K >> 6;

    auto load_tile = [&](int kt, int s){
        #pragma unroll
        for(int i = tid; i < BM*8; i += 128){
            int m = i >> 3, k8 = (i & 7) << 3;
            uint32_t dst = sAb + (s*ASZ + m*ASTR + k8) * 2;
            asm volatile("cp.async.cg.shared.global [%0], [%1], 16;"
                :: "r"(dst), "l"(Wt + (size_t)m*K + kt*64 + k8));
        }
        #pragma unroll
        for(int i = tid; i < 1024; i += 128){
            int kr = i >> 4, c8 = (i & 15) << 3;
            int p = n0 + c8;
            const __half* src = (p < PP) ? (Xb + (size_t)(kt*64 + kr)*PP + p) : Xb;
            uint32_t sz = (p < PP) ? 16u : 0u;
            uint32_t dst = sBb + (s*BSZ + kr*BSTR + c8) * 2;
            asm volatile("cp.async.cg.shared.global [%0], [%1], 16, %2;"
                :: "r"(dst), "l"(src), "r"(sz));
        }
        asm volatile("cp.async.commit_group;" ::: "memory");
    };

    load_tile(0, 0);

    for(int kt = 0; kt < NK; kt++){
        const int s = kt & 1;
        if(kt + 1 < NK){
            load_tile(kt + 1, 1 - s);
            asm volatile("cp.async.wait_group 1;" ::: "memory");
        } else {
            asm volatile("cp.async.wait_group 0;" ::: "memory");
        }
        __syncthreads();

        const uint32_t aBase = sAb + s*ASZ*2;
        const uint32_t bBase = sBb + s*BSZ*2;
        #pragma unroll
        for(int kk = 0; kk < BK; kk += 16){
            uint32_t a[MT][4], bb[NT][2];
            #pragma unroll
            for(int m=0;m<MT;m++){
                int mr = warpM*64 + m*16;
                uint32_t addr = aBase + (uint32_t)(((mr + l8 + lb1*8)*ASTR + kk + lb2*8)*2);
                ldsm4(a[m][0],a[m][1],a[m][2],a[m][3], addr);
            }
            #pragma unroll
            for(int np=0; np<4; np++){
                int nc = warpN*64 + np*16;
                uint32_t addr = bBase + (uint32_t)(((kk + lb1*8 + l8)*BSTR + nc + lb2*8)*2);
                ldsm4t(bb[2*np][0], bb[2*np][1], bb[2*np+1][0], bb[2*np+1][1], addr);
            }
            #pragma unroll
            for(int m=0;m<MT;m++)
                #pragma unroll
                for(int n=0;n<NT;n++)
                    mma16(c[m][n], a[m][0],a[m][1],a[m][2],a[m][3], bb[n][0],bb[n][1]);
        }
        __syncthreads();
    }

    const float rs = rsqrtf(1.0f + EPSV);
    #pragma unroll
    for(int m=0;m<MT;m++){
        #pragma unroll
        for(int half_=0; half_<2; half_++){
            const int row = m0 + warpM*64 + m*16 + gid + half_*8;
            float add0=bias[row], sc=1.f, sh=0.f;
            if(EPI==EPI_BN_H){ sc=gamma[row]*rs; sh=beta[row]; }
            #pragma unroll
            for(int n=0;n<NT;n++){
                const int p = n0 + warpN*64 + n*8 + 2*tig;
                if(p < PP){
                    float y0 = c[m][n][half_*2+0];
                    float y1 = c[m][n][half_*2+1];
                    if(EPI==EPI_PAD){
                        float* Y = (float*)Yv;
                        y0 += add0; y1 += add0;
                        int h=p/HH, w=p-h*HH;
                        float* yb = Y + ((size_t)(b*CC+row)*OUTH)*OUTH;
                        yb[(h+1)*OUTH + w+1] = y0;
                        int p1=p+1, h1=p1/HH, w1=p1-h1*HH;
                        yb[(h1+1)*OUTH + w1+1] = y1;
                    } else {
                        y0=(y0+add0)*sc+sh; y1=(y1+add0)*sc+sh;
                        __half* Yh = (__half*)Yv;
                        *reinterpret_cast<__half2*>(Yh + ((size_t)b*Mtot + row)*PP + p)
                            = __floats2half2_rn(y0, y1);
                    }
                }
            }
        }
    }
}

// ================= tensor-core attention (2-group pipelined loads) =================
__global__ __launch_bounds__(128)
void attn_tc(const __half* __restrict__ lqh, const __half* __restrict__ kvsh,
             const __half* __restrict__ kvfqh, const float* __restrict__ gqs,
             __half* __restrict__ fH)
{
    constexpr int STR = 72;
    __shared__ __align__(16) __half sm[5*64*STR];
    __half* sQ  = sm;
    __half* sK  = sm + 1*64*STR;
    __half* sGK = sm + 2*64*STR;
    __half* sV  = sm + 3*64*STR;
    __half* sGV = sm + 4*64*STR;

    const int bc = blockIdx.x;
    const int b = bc >> 8, ch = bc & 255;
    const size_t base_q = (size_t)bc * PP;
    const size_t base_k = ((size_t)(b*512 + ch)) * PP;
    const size_t base_v = base_k + (size_t)256 * PP;
    const int tid = threadIdx.x, wid = tid>>5, lane = tid&31;
    const int gid = lane>>2, tig = lane&3;
    const int l8 = lane&7, lb1 = (lane>>3)&1, lb2 = lane>>4;

    uint32_t* usm = (uint32_t*)sm;
    // zero pads
    for(int i = tid; i < 5*64*4; i += 128){
        int arr = i >> 8, rem = i & 255;
        int r = rem >> 2, j = rem & 3;
        usm[arr*64*36 + r*36 + 28 + j] = 0;
    }
    for(int i = tid; i < 5*8*28; i += 128){
        int arr = i / 224, rem = i - arr*224;
        int r = 56 + rem/28, j = rem - (rem/28)*28;
        usm[arr*64*36 + r*36 + j] = 0;
    }
    const uint32_t smB = smem_u32(sm);
    // group 1: Q, K
    {
        const __half* s0 = lqh + base_q;
        const __half* s1 = kvsh + base_k;
        for(int i = tid; i < 56*7; i += 128){
            int r = i/7, chx = i - r*7;
            asm volatile("cp.async.cg.shared.global [%0], [%1], 16;"
                :: "r"(smB + (0*64*STR + r*STR + chx*8)*2), "l"(s0 + (size_t)r*HH + chx*8));
            asm volatile("cp.async.cg.shared.global [%0], [%1], 16;"
                :: "r"(smB + (1*64*STR + r*STR + chx*8)*2), "l"(s1 + (size_t)r*HH + chx*8));
        }
        asm volatile("cp.async.commit_group;" ::: "memory");
    }
    // group 2: GK, V, GV
    {
        const __half* s2 = kvfqh + base_k;
        const __half* s3 = kvsh + base_v;
        const __half* s4 = kvfqh + base_v;
        for(int i = tid; i < 56*7; i += 128){
            int r = i/7, chx = i - r*7;
            asm volatile("cp.async.cg.shared.global [%0], [%1], 16;"
                :: "r"(smB + (2*64*STR + r*STR + chx*8)*2), "l"(s2 + (size_t)r*HH + chx*8));
            asm volatile("cp.async.cg.shared.global [%0], [%1], 16;"
                :: "r"(smB + (3*64*STR + r*STR + chx*8)*2), "l"(s3 + (size_t)r*HH + chx*8));
            asm volatile("cp.async.cg.shared.global [%0], [%1], 16;"
                :: "r"(smB + (4*64*STR + r*STR + chx*8)*2), "l"(s4 + (size_t)r*HH + chx*8));
        }
        asm volatile("cp.async.commit_group;" ::: "memory");
    }
    asm volatile("cp.async.wait_group 1;" ::: "memory");
    __syncthreads();

    const uint32_t qB = smem_u32(sQ), kB = smem_u32(sK), vB = smem_u32(sV);
    const uint32_t gkB = smem_u32(sGK), gvB = smem_u32(sGV);
    const int m0 = wid*16;
    const uint32_t aOff = (uint32_t)(((m0 + l8 + lb1*8)*STR)*2);
    const uint32_t bRowN = (uint32_t)((l8 + lb2*8)*STR*2);

    // ---- S = Q @ K^T ----
    float c[8][4];
    #pragma unroll
    for(int n=0;n<8;n++){ c[n][0]=0; c[n][1]=0; c[n][2]=0; c[n][3]=0; }
    #pragma unroll
    for(int kk = 0; kk < 64; kk += 16){
        uint32_t a0,a1,a2,a3;
        ldsm4(a0,a1,a2,a3, qB + aOff + (kk + lb2*8)*2);
        uint32_t bb[8][2];
        #pragma unroll
        for(int np=0;np<4;np++){
            uint32_t addr = kB + bRowN + (uint32_t)((np*16*STR + kk + lb1*8)*2);
            ldsm4(bb[2*np][0], bb[2*np][1], bb[2*np+1][0], bb[2*np+1][1], addr);
        }
        #pragma unroll
        for(int n=0;n<8;n++)
            mma16(c[n], a0,a1,a2,a3, bb[n][0], bb[n][1]);
    }

    // ---- local softmax, P -> sQ (warp-private rows) ----
    #pragma unroll
    for(int half_=0; half_<2; half_++){
        const int h2 = half_*2;
        float m = -1e30f;
        #pragma unroll
        for(int n=0;n<7;n++) m = fmaxf(m, fmaxf(c[n][h2], c[n][h2+1]));
        m = fmaxf(m, __shfl_xor_sync(0xffffffffu, m, 1));
        m = fmaxf(m, __shfl_xor_sync(0xffffffffu, m, 2));
        float s = 0.f;
        #pragma unroll
        for(int n=0;n<7;n++){
            float e0 = __expf((c[n][h2  ] - m)*SCALEV);
            float e1 = __expf((c[n][h2+1] - m)*SCALEV);
            c[n][h2]=e0; c[n][h2+1]=e1; s += e0+e1;
        }
        s += __shfl_xor_sync(0xffffffffu, s, 1);
        s += __shfl_xor_sync(0xffffffffu, s, 2);
        const float inv = 1.f/s;
        const int row = m0 + gid + half_*8;
        #pragma unroll
        for(int n=0;n<8;n++){
            __half2 hv = (n<7) ? __floats2half2_rn(c[n][h2]*inv, c[n][h2+1]*inv)
                               : __floats2half2_rn(0.f, 0.f);
            *reinterpret_cast<__half2*>(sQ + row*STR + n*8 + 2*tig) = hv;
        }
    }

    asm volatile("cp.async.wait_group 0;" ::: "memory");
    __syncthreads();

    // ---- global softmax: parallel, warp-private rows of sGK ----
    {
        const float gq = gqs[bc];
        #pragma unroll
        for(int half_=0; half_<2; half_++){
            const int row = m0 + gid + half_*8;
            float v[7][2];
            float m = -1e30f;
            #pragma unroll
            for(int n=0;n<7;n++){
                __half2 hv = *reinterpret_cast<__half2*>(sGK + row*STR + n*8 + 2*tig);
                v[n][0] = gq*__low2float(hv);
                v[n][1] = gq*__high2float(hv);
                m = fmaxf(m, fmaxf(v[n][0], v[n][1]));
            }
            m = fmaxf(m, __shfl_xor_sync(0xffffffffu, m, 1));
            m = fmaxf(m, __shfl_xor_sync(0xffffffffu, m, 2));
            float s = 0.f;
            #pragma unroll
            for(int n=0;n<7;n++){
                v[n][0]=__expf(v[n][0]-m); v[n][1]=__expf(v[n][1]-m);
                s += v[n][0]+v[n][1];
            }
            s += __shfl_xor_sync(0xffffffffu, s, 1);
            s += __shfl_xor_sync(0xffffffffu, s, 2);
            const float inv = 1.f/s;
            #pragma unroll
            for(int n=0;n<8;n++){
                __half2 hv = (n<7) ? __floats2half2_rn(v[n][0]*inv, v[n][1]*inv)
                                   : __floats2half2_rn(0.f, 0.f);
                *reinterpret_cast<__half2*>(sGK + row*STR + n*8 + 2*tig) = hv;
            }
        }
    }
    __syncwarp();

    // ---- O = P@V^T + GS@GV^T ----
    #pragma unroll
    for(int n=0;n<8;n++){ c[n][0]=0; c[n][1]=0; c[n][2]=0; c[n][3]=0; }
    #pragma unroll
    for(int kk = 0; kk < 64; kk += 16){
        uint32_t a0,a1,a2,a3;
        ldsm4(a0,a1,a2,a3, qB + aOff + (kk + lb2*8)*2);
        uint32_t bb[8][2];
        #pragma unroll
        for(int np=0;np<4;np++){
            int nc = np*16;
            uint32_t addr = vB + (uint32_t)(((kk + lb1*8 + l8)*STR + nc + lb2*8)*2);
            ldsm4t(bb[2*np][0], bb[2*np][1], bb[2*np+1][0], bb[2*np+1][1], addr);
        }
        #pragma unroll
        for(int n=0;n<8;n++)
            mma16(c[n], a0,a1,a2,a3, bb[n][0], bb[n][1]);
    }
    #pragma unroll
    for(int kk = 0; kk < 64; kk += 16){
        uint32_t a0,a1,a2,a3;
        ldsm4(a0,a1,a2,a3, gkB + aOff + (kk + lb2*8)*2);
        uint32_t bb[8][2];
        #pragma unroll
        for(int np=0;np<4;np++){
            int nc = np*16;
            uint32_t addr = gvB + (uint32_t)(((kk + lb1*8 + l8)*STR + nc + lb2*8)*2);
            ldsm4t(bb[2*np][0], bb[2*np][1], bb[2*np+1][0], bb[2*np+1][1], addr);
        }
        #pragma unroll
        for(int n=0;n<8;n++)
            mma16(c[n], a0,a1,a2,a3, bb[n][0], bb[n][1]);
    }

    #pragma unroll
    for(int half_=0; half_<2; half_++){
        const int row = m0 + gid + half_*8;
        if(row < 56){
            #pragma unroll
            for(int n=0;n<7;n++){
                *reinterpret_cast<__half2*>(fH + base_q + row*HH + n*8 + 2*tig)
                    = __floats2half2_rn(c[n][half_*2], c[n][half_*2+1]);
            }
        }
    }
}

// ================= merged setup =================
#define NCVT  12544
#define NPREP 704
#define NBORD 3648
#define NMEAN 4096

__global__ void setup_kernel(const float* __restrict__ x_s, const float* __restrict__ x_fq,
                             const float* __restrict__ x_mt,
                             const float* __restrict__ lk_w, const float* __restrict__ lv_w,
                             const float* __restrict__ gk_w, const float* __restrict__ gv_w,
                             const float* __restrict__ la_w1, const float* __restrict__ la_w2,
                             const float* __restrict__ c1_w,
                             const float* __restrict__ lk_b, const float* __restrict__ gk_b,
                             const float* __restrict__ c1_b,
                             float* __restrict__ out)
{
    __shared__ float red[256];
    const int blk = blockIdx.x, tid = threadIdx.x;

    if(blk < NCVT){
        const int idx = blk*256 + tid;
        float4 v = reinterpret_cast<const float4*>(x_s)[idx];
        __half2 h0 = __floats2half2_rn(v.x, v.y);
        __half2 h1 = __floats2half2_rn(v.z, v.w);
        uint2 o;
        o.x = *reinterpret_cast<uint32_t*>(&h0);
        o.y = *reinterpret_cast<uint32_t*>(&h1);
        reinterpret_cast<uint2*>(g_xH)[idx] = o;
        float4 w = reinterpret_cast<const float4*>(x_fq)[idx];
        __half2 g0 = __floats2half2_rn(w.x, w.y);
        __half2 g1 = __floats2half2_rn(w.z, w.w);
        uint2 o2;
        o2.x = *reinterpret_cast<uint32_t*>(&g0);
        o2.y = *reinterpret_cast<uint32_t*>(&g1);
        reinterpret_cast<uint2*>(g_xH + NXE)[idx] = o2;
    } else if(blk < NCVT + NPREP){
        const int i = (blk - NCVT)*256 + tid;
        if(i < 131072){
            g_wh[i]          = __float2half(i < 65536 ? lk_w[i] : lv_w[i-65536]);
            g_wh[131072 + i] = __float2half(i < 65536 ? gk_w[i] : gv_w[i-65536]);
        } else if(i < 163840){
            int j = i - 131072;             // la1 padded to 128 rows
            int row = j >> 8, col = j & 255;
            g_wh[262144 + j] = (row < ICC) ? __float2half(la_w1[row*CC + col])
                                           : __float2half(0.f);
        } else if(i < 180224){
            int j = i - 163840;
            g_wh[294912 + j] = __float2half(la_w2[j]);
        }
        if(i < 65536) g_wh[311296 + i] = __float2half(c1_w[i]);
        if(i < 512){
            g_sb[i]       = (i < 256) ? lk_b[i] : 0.f;
            g_sb[512 + i] = (i < 256) ? gk_b[i] : 0.f;
        }
    } else if(blk < NCVT + NPREP + NBORD){
        const int idx = (blk - NCVT - NPREP)*256 + tid;
        const int total = BB*CC*228;
        if(idx < total){
            const int bc = idx / 228, j = idx - bc*228;
            int h, w;
            if(j < 58){ h = 0; w = j; }
            else if(j < 116){ h = 57; w = j - 58; }
            else { int j2 = j - 116; h = 1 + (j2 >> 1); w = (j2 & 1) * 57; }
            out[((size_t)bc*OUTH + h)*OUTH + w] = c1_b[bc & 255];
        }
    } else {
        const int bc = blk - NCVT - NPREP - NBORD;
        const float* p = x_mt + (size_t)bc*PP;
        float s = 0.f;
        for(int i = tid; i < PP; i += 256) s += p[i];
        red[tid] = s; __syncthreads();
        for(int o = 128; o > 0; o >>= 1){
            if(tid < o) red[tid] += red[tid + o];
            __syncthreads();
        }
        if(tid == 0) g_xbar[bc] = red[0]*(1.0f/PP);
    }
}

// ---------------- launch ----------------
extern "C" void kernel_launch(void* const* d_in, const int* in_sizes, int n_in,
                              void* d_out, int out_size)
{
    const float* x_s  =(const float*)d_in[0];
    const float* x_fq =(const float*)d_in[1];
    const float* x_mt =(const float*)d_in[2];
    const float* la_w1=(const float*)d_in[3];
    const float* la_b1=(const float*)d_in[4];
    const float* la_g1=(const float*)d_in[5];
    const float* la_be1=(const float*)d_in[6];
    const float* la_w2=(const float*)d_in[7];
    const float* la_b2=(const float*)d_in[8];
    const float* la_g2=(const float*)d_in[9];
    const float* la_be2=(const float*)d_in[10];
    const float* lk_w =(const float*)d_in[11];
    const float* lk_b =(const float*)d_in[12];
    const float* lv_w =(const float*)d_in[13];
    const float* ga_w1=(const float*)d_in[14];
    const float* ga_b1=(const float*)d_in[15];
    const float* ga_g1=(const float*)d_in[16];
    const float* ga_be1=(const float*)d_in[17];
    const float* ga_w2=(const float*)d_in[18];
    const float* ga_b2=(const float*)d_in[19];
    const float* ga_g2=(const float*)d_in[20];
    const float* ga_be2=(const float*)d_in[21];
    const float* gk_w =(const float*)d_in[22];
    const float* gk_b =(const float*)d_in[23];
    const float* gv_w =(const float*)d_in[24];
    const float* c11_w=(const float*)d_in[25];
    const float* c11_b=(const float*)d_in[26];
    const float* c1_w =(const float*)d_in[27];
    const float* c1_b =(const float*)d_in[28];
    float* out=(float*)d_out;

    __half *t1H,*lqh,*kv,*fH,*wh;
    float *gqs;
    cudaGetSymbolAddress((void**)&t1H, g_t1H);
    cudaGetSymbolAddress((void**)&lqh, g_lqh);
    cudaGetSymbolAddress((void**)&kv,  g_kv);
    cudaGetSymbolAddress((void**)&fH,  g_fH);
    cudaGetSymbolAddress((void**)&gqs, g_gqs);
    cudaGetSymbolAddress((void**)&wh,  g_wh);

    const int NB = (PP + 127)/128;   // 25
    const int SM128 = 2*(128*72 + 64*136)*2;
    cudaFuncSetAttribute(mega_kernel,       cudaFuncAttributeMaxDynamicSharedMemorySize, SM128);
    cudaFuncSetAttribute(hgemm<EPI_BN_H>,   cudaFuncAttributeMaxDynamicSharedMemorySize, SM128);
    cudaFuncSetAttribute(hgemm<EPI_PAD>,    cudaFuncAttributeMaxDynamicSharedMemorySize, SM128);

    // 1: merged setup
    setup_kernel<<<NCVT + NPREP + NBORD + NMEAN, 256>>>(
        x_s, x_fq, x_mt, lk_w, lv_w, gk_w, gv_w, la_w1, la_w2, c1_w,
        lk_b, gk_b, c1_b, out);
    // 2: mega (KV + t1 + gq)
    {   dim3 g(NB, 6, 2*BB);
        mega_kernel<<<g, 128, SM128>>>(la_b1, la_g1, la_be1,
                                       c11_w, c11_b, ga_w1, ga_b1, ga_g1, ga_be1,
                                       ga_w2, ga_b2, ga_g2, ga_be2);
    }
    // 3: l_q
    {   dim3 g(NB, CC/128, BB);
        hgemm<EPI_BN_H><<<g, 128, SM128>>>(wh + 294912, t1H, lqh, ICC, CC,
                                           la_b2, la_g2, la_be2);
    }
    // 4: attention  <-- profiled
    attn_tc<<<BB*CC, 128>>>(lqh, kv, kv + KVN, gqs, fH);
    // 5: padded output conv
    {   dim3 g(NB, CC/128, BB);
        hgemm<EPI_PAD><<<g, 128, SM128>>>(wh + 311296, fH, out, CC, CC,
                                          c1_b, c1_b, c1_b);
    }
}

// round 16
// speedup vs baseline: 1.2058x; 1.0194x over previous
#include <cuda_runtime.h>
#include <cuda_fp16.h>
#include <math.h>
#include <stdint.h>

#define BB   16
#define CC   256
#define ICC  64
#define HH   56
#define PP   (HH*HH)
#define OUTH 58
#define EPSV 1e-5f
#define SCALEV (1.0f/896.0f)

#define NXE (BB*CC*PP)
#define KVN ((size_t)BB*2*CC*PP)

__device__ __half g_xH [2*NXE];
__device__ __half g_t1H[BB*ICC*PP];
__device__ __half g_lqh[BB*CC*PP];
__device__ __half g_kv [2*BB*2*CC*PP];
__device__ __half g_fH [BB*CC*PP];
__device__ float  g_xbar[BB*CC];
__device__ float  g_gqs [BB*CC];
__device__ __half g_wh  [376832];
__device__ float  g_sb  [1024];

#define EPI_PAD    4
#define EPI_BN_H   6

__device__ __forceinline__ uint32_t smem_u32(const void* p){
    uint32_t a;
    asm("{ .reg .u64 t; cvta.to.shared.u64 t, %1; cvt.u32.u64 %0, t; }":"=r"(a):"l"(p));
    return a;
}
__device__ __forceinline__ void mma16(float c[4],
    uint32_t a0, uint32_t a1, uint32_t a2, uint32_t a3, uint32_t b0, uint32_t b1){
    asm volatile(
        "mma.sync.aligned.m16n8k16.row.col.f32.f16.f16.f32 "
        "{%0,%1,%2,%3}, {%4,%5,%6,%7}, {%8,%9}, {%0,%1,%2,%3};"
        : "+f"(c[0]),"+f"(c[1]),"+f"(c[2]),"+f"(c[3])
        : "r"(a0),"r"(a1),"r"(a2),"r"(a3),"r"(b0),"r"(b1));
}
__device__ __forceinline__ void ldsm4(uint32_t& r0, uint32_t& r1, uint32_t& r2, uint32_t& r3,
                                      uint32_t addr){
    asm volatile("ldmatrix.sync.aligned.m8n8.x4.shared.b16 {%0,%1,%2,%3}, [%4];"
        : "=r"(r0),"=r"(r1),"=r"(r2),"=r"(r3) : "r"(addr));
}
__device__ __forceinline__ void ldsm4t(uint32_t& r0, uint32_t& r1, uint32_t& r2, uint32_t& r3,
                                       uint32_t addr){
    asm volatile("ldmatrix.sync.aligned.m8n8.x4.trans.shared.b16 {%0,%1,%2,%3}, [%4];"
        : "=r"(r0),"=r"(r1),"=r"(r2),"=r"(r3) : "r"(addr));
}

// ================= mega kernel: KV GEMM (y<4) + t1 GEMM (y==4) + gq MLP (y==5) =================
__global__ __launch_bounds__(128)
void mega_kernel(const float* __restrict__ la_b1, const float* __restrict__ la_g1,
                 const float* __restrict__ la_be1,
                 const float* __restrict__ c11_w, const float* __restrict__ c11_b,
                 const float* __restrict__ ga_w1, const float* __restrict__ ga_b1,
                 const float* __restrict__ ga_g1, const float* __restrict__ ga_be1,
                 const float* __restrict__ ga_w2, const float* __restrict__ ga_b2,
                 const float* __restrict__ ga_g2, const float* __restrict__ ga_be2)
{
    constexpr int BM = 128, BK = 64;
    constexpr int MT = 4, NT = 8;
    constexpr int ASTR = 72, BSTR = 136;
    constexpr int ASZ = BM * ASTR;
    constexpr int BSZ = BK * BSTR;

    extern __shared__ __align__(16) __half dsm[];

    const float rs = rsqrtf(1.0f + EPSV);
    const int tid = threadIdx.x;

    if(blockIdx.y == 5){
        if(blockIdx.x >= 16 || blockIdx.z > 0) return;
        float* fs = (float*)dsm;
        float* xb = fs; float* pv = fs + 256; float* tv = fs + 512;
        const int b = blockIdx.x;
        xb[tid]     = g_xbar[b*CC + tid];
        xb[tid+128] = g_xbar[b*CC + tid + 128];
        __syncthreads();
        for(int cc = tid; cc < 256; cc += 128){
            float d = 0.f; const float* wr = c11_w + (size_t)cc*CC;
            for(int c = 0; c < CC; c++) d = fmaf(wr[c], xb[c], d);
            pv[cc] = d + c11_b[cc];
        }
        __syncthreads();
        if(tid < ICC){
            float d = 0.f; const float* wr = ga_w1 + (size_t)tid*CC;
            for(int c = 0; c < CC; c++) d = fmaf(wr[c], pv[c], d);
            d = (d + ga_b1[tid])*(ga_g1[tid]*rs) + ga_be1[tid];
            tv[tid] = (d >= 0.f) ? d : 0.2f*d;
        }
        __syncthreads();
        for(int cc = tid; cc < 256; cc += 128){
            float d = 0.f; const float* wr = ga_w2 + (size_t)cc*ICC;
            for(int i = 0; i < ICC; i++) d = fmaf(wr[i], tv[i], d);
            d = (d + ga_b2[cc])*(ga_g2[cc]*rs) + ga_be2[cc];
            g_gqs[b*CC + cc] = d*SCALEV;
        }
        return;
    }

    const bool t1m = (blockIdx.y == 4);
    if(t1m && blockIdx.z >= BB) return;

    __half* sA = dsm;
    __half* sB = dsm + 2*ASZ;
    const int wid = tid >> 5, lane = tid & 31;
    const int gid = lane >> 2, tig = lane & 3;
    const int l8 = lane & 7, lb1 = (lane >> 3) & 1, lb2 = lane >> 4;
    const int warpM = wid >> 1, warpN = wid & 1;
    const int n0 = blockIdx.x * 128;
    const int m0 = t1m ? 0 : blockIdx.y * BM;
    const int which = t1m ? 0 : (blockIdx.z / BB);
    const int b = t1m ? blockIdx.z : (blockIdx.z - which * BB);
    const int K = CC;

    const __half* Wt = t1m ? (g_wh + 262144)
                           : (g_wh + which*131072 + (size_t)m0 * K);
    const __half* Xb = g_xH + which*(size_t)NXE + (size_t)b * K * PP;
    const uint32_t sAb = smem_u32(sA);
    const uint32_t sBb = smem_u32(sB);

    float c[MT][NT][4];
    #pragma unroll
    for(int m=0;m<MT;m++)
        #pragma unroll
        for(int n=0;n<NT;n++)
            #pragma unroll
            for(int q=0;q<4;q++) c[m][n][q]=0.f;

    const int NK = K >> 6;

    auto load_tile = [&](int kt, int s){
        #pragma unroll
        for(int i = tid; i < BM*8; i += 128){
            int m = i >> 3, k8 = (i & 7) << 3;
            uint32_t dst = sAb + (s*ASZ + m*ASTR + k8) * 2;
            asm volatile("cp.async.cg.shared.global [%0], [%1], 16;"
                :: "r"(dst), "l"(Wt + (size_t)m*K + kt*64 + k8));
        }
        #pragma unroll
        for(int i = tid; i < 1024; i += 128){
            int kr = i >> 4, c8 = (i & 15) << 3;
            int p = n0 + c8;
            const __half* src = (p < PP) ? (Xb + (size_t)(kt*64 + kr)*PP + p) : Xb;
            uint32_t sz = (p < PP) ? 16u : 0u;
            uint32_t dst = sBb + (s*BSZ + kr*BSTR + c8) * 2;
            asm volatile("cp.async.cg.shared.global [%0], [%1], 16, %2;"
                :: "r"(dst), "l"(src), "r"(sz));
        }
        asm volatile("cp.async.commit_group;" ::: "memory");
    };

    load_tile(0, 0);

    for(int kt = 0; kt < NK; kt++){
        const int s = kt & 1;
        if(kt + 1 < NK){
            load_tile(kt + 1, 1 - s);
            asm volatile("cp.async.wait_group 1;" ::: "memory");
        } else {
            asm volatile("cp.async.wait_group 0;" ::: "memory");
        }
        __syncthreads();

        const uint32_t aBase = sAb + s*ASZ*2;
        const uint32_t bBase = sBb + s*BSZ*2;
        #pragma unroll
        for(int kk = 0; kk < BK; kk += 16){
            uint32_t a[MT][4], bb[NT][2];
            #pragma unroll
            for(int m=0;m<MT;m++){
                int mr = warpM*64 + m*16;
                uint32_t addr = aBase + (uint32_t)(((mr + l8 + lb1*8)*ASTR + kk + lb2*8)*2);
                ldsm4(a[m][0],a[m][1],a[m][2],a[m][3], addr);
            }
            #pragma unroll
            for(int np=0; np<4; np++){
                int nc = warpN*64 + np*16;
                uint32_t addr = bBase + (uint32_t)(((kk + lb1*8 + l8)*BSTR + nc + lb2*8)*2);
                ldsm4t(bb[2*np][0], bb[2*np][1], bb[2*np+1][0], bb[2*np+1][1], addr);
            }
            #pragma unroll
            for(int m=0;m<MT;m++)
                #pragma unroll
                for(int n=0;n<NT;n++)
                    mma16(c[m][n], a[m][0],a[m][1],a[m][2],a[m][3], bb[n][0],bb[n][1]);
        }
        __syncthreads();
    }

    #pragma unroll
    for(int m=0;m<MT;m++){
        #pragma unroll
        for(int half_=0; half_<2; half_++){
            const int row = warpM*64 + m*16 + gid + half_*8;
            if(t1m){
                if(row >= ICC) continue;
                float add0 = la_b1[row], sc = la_g1[row]*rs, sh = la_be1[row];
                #pragma unroll
                for(int n=0;n<NT;n++){
                    const int p = n0 + warpN*64 + n*8 + 2*tig;
                    if(p < PP){
                        float y0 = (c[m][n][half_*2+0] + add0)*sc + sh;
                        float y1 = (c[m][n][half_*2+1] + add0)*sc + sh;
                        y0 = (y0>=0.f)? y0 : 0.2f*y0;
                        y1 = (y1>=0.f)? y1 : 0.2f*y1;
                        *reinterpret_cast<__half2*>(g_t1H + ((size_t)b*ICC + row)*PP + p)
                            = __floats2half2_rn(y0, y1);
                    }
                }
            } else {
                const int grow = m0 + row;
                const float add0 = g_sb[which*512 + grow];
                #pragma unroll
                for(int n=0;n<NT;n++){
                    const int p = n0 + warpN*64 + n*8 + 2*tig;
                    if(p < PP){
                        float y0 = c[m][n][half_*2+0] + add0;
                        float y1 = c[m][n][half_*2+1] + add0;
                        *reinterpret_cast<__half2*>(
                            g_kv + which*KVN + ((size_t)b*512 + grow)*PP + p)
                            = __floats2half2_rn(y0, y1);
                    }
                }
            }
        }
    }
}

// ================= hgemm (lq, c1) =================
template<int EPI>
__global__ __launch_bounds__(128)
void hgemm(const __half* __restrict__ W, const __half* __restrict__ X,
           void* __restrict__ Yv, int K, int Mtot,
           const float* __restrict__ bias,
           const float* __restrict__ gamma,
           const float* __restrict__ beta)
{
    constexpr int BM = 128, BK = 64;
    constexpr int MT = 4, NT = 8;
    constexpr int ASTR = 72, BSTR = 136;
    constexpr int ASZ = BM * ASTR;
    constexpr int BSZ = BK * BSTR;

    extern __shared__ __align__(16) __half dsm[];
    __half* sA = dsm;
    __half* sB = dsm + 2*ASZ;

    const int tid = threadIdx.x, wid = tid >> 5, lane = tid & 31;
    const int gid = lane >> 2, tig = lane & 3;
    const int l8 = lane & 7, lb1 = (lane >> 3) & 1, lb2 = lane >> 4;
    const int warpM = wid >> 1, warpN = wid & 1;
    const int m0 = blockIdx.y * BM, n0 = blockIdx.x * 128;
    const int b = blockIdx.z;

    const __half* Wt = W + (size_t)m0 * K;
    const __half* Xb = X + (size_t)b * K * PP;
    const uint32_t sAb = smem_u32(sA);
    const uint32_t sBb = smem_u32(sB);

    float c[MT][NT][4];
    #pragma unroll
    for(int m=0;m<MT;m++)
        #pragma unroll
        for(int n=0;n<NT;n++)
            #pragma unroll
            for(int q=0;q<4;q++) c[m][n][q]=0.f;

    const int NK = K >> 6;

    auto load_tile = [&](int kt, int s){
        #pragma unroll
        for(int i = tid; i < BM*8; i += 128){
            int m = i >> 3, k8 = (i & 7) << 3;
            uint32_t dst = sAb + (s*ASZ + m*ASTR + k8) * 2;
            asm volatile("cp.async.cg.shared.global [%0], [%1], 16;"
                :: "r"(dst), "l"(Wt + (size_t)m*K + kt*64 + k8));
        }
        #pragma unroll
        for(int i = tid; i < 1024; i += 128){
            int kr = i >> 4, c8 = (i & 15) << 3;
            int p = n0 + c8;
            const __half* src = (p < PP) ? (Xb + (size_t)(kt*64 + kr)*PP + p) : Xb;
            uint32_t sz = (p < PP) ? 16u : 0u;
            uint32_t dst = sBb + (s*BSZ + kr*BSTR + c8) * 2;
            asm volatile("cp.async.cg.shared.global [%0], [%1], 16, %2;"
                :: "r"(dst), "l"(src), "r"(sz));
        }
        asm volatile("cp.async.commit_group;" ::: "memory");
    };

    load_tile(0, 0);

    for(int kt = 0; kt < NK; kt++){
        const int s = kt & 1;
        if(kt + 1 < NK){
            load_tile(kt + 1, 1 - s);
            asm volatile("cp.async.wait_group 1;" ::: "memory");
        } else {
            asm volatile("cp.async.wait_group 0;" ::: "memory");
        }
        __syncthreads();

        const uint32_t aBase = sAb + s*ASZ*2;
        const uint32_t bBase = sBb + s*BSZ*2;
        #pragma unroll
        for(int kk = 0; kk < BK; kk += 16){
            uint32_t a[MT][4], bb[NT][2];
            #pragma unroll
            for(int m=0;m<MT;m++){
                int mr = warpM*64 + m*16;
                uint32_t addr = aBase + (uint32_t)(((mr + l8 + lb1*8)*ASTR + kk + lb2*8)*2);
                ldsm4(a[m][0],a[m][1],a[m][2],a[m][3], addr);
            }
            #pragma unroll
            for(int np=0; np<4; np++){
                int nc = warpN*64 + np*16;
                uint32_t addr = bBase + (uint32_t)(((kk + lb1*8 + l8)*BSTR + nc + lb2*8)*2);
                ldsm4t(bb[2*np][0], bb[2*np][1], bb[2*np+1][0], bb[2*np+1][1], addr);
            }
            #pragma unroll
            for(int m=0;m<MT;m++)
                #pragma unroll
                for(int n=0;n<NT;n++)
                    mma16(c[m][n], a[m][0],a[m][1],a[m][2],a[m][3], bb[n][0],bb[n][1]);
        }
        __syncthreads();
    }

    const float rs = rsqrtf(1.0f + EPSV);
    #pragma unroll
    for(int m=0;m<MT;m++){
        #pragma unroll
        for(int half_=0; half_<2; half_++){
            const int row = m0 + warpM*64 + m*16 + gid + half_*8;
            float add0=bias[row], sc=1.f, sh=0.f;
            if(EPI==EPI_BN_H){ sc=gamma[row]*rs; sh=beta[row]; }
            #pragma unroll
            for(int n=0;n<NT;n++){
                const int p = n0 + warpN*64 + n*8 + 2*tig;
                if(p < PP){
                    float y0 = c[m][n][half_*2+0];
                    float y1 = c[m][n][half_*2+1];
                    if(EPI==EPI_PAD){
                        float* Y = (float*)Yv;
                        y0 += add0; y1 += add0;
                        int h=p/HH, w=p-h*HH;
                        float* yb = Y + ((size_t)(b*CC+row)*OUTH)*OUTH;
                        yb[(h+1)*OUTH + w+1] = y0;
                        int p1=p+1, h1=p1/HH, w1=p1-h1*HH;
                        yb[(h1+1)*OUTH + w1+1] = y1;
                    } else {
                        y0=(y0+add0)*sc+sh; y1=(y1+add0)*sc+sh;
                        __half* Yh = (__half*)Yv;
                        *reinterpret_cast<__half2*>(Yh + ((size_t)b*Mtot + row)*PP + p)
                            = __floats2half2_rn(y0, y1);
                    }
                }
            }
        }
    }
}

// ================= tensor-core attention (4 smem buffers, 6 CTAs/SM) =================
// B1=Q->P, B2=K->V, B3=GK->GS, B4=GV
__global__ __launch_bounds__(128)
void attn_tc(const __half* __restrict__ lqh, const __half* __restrict__ kvsh,
             const __half* __restrict__ kvfqh, const float* __restrict__ gqs,
             __half* __restrict__ fH)
{
    constexpr int STR = 72;
    __shared__ __align__(16) __half sm[4*64*STR];
    __half* sB1 = sm;
    __half* sB2 = sm + 1*64*STR;
    __half* sB3 = sm + 2*64*STR;
    __half* sB4 = sm + 3*64*STR;

    const int bc = blockIdx.x;
    const int b = bc >> 8, ch = bc & 255;
    const size_t base_q = (size_t)bc * PP;
    const size_t base_k = ((size_t)(b*512 + ch)) * PP;
    const size_t base_v = base_k + (size_t)256 * PP;
    const int tid = threadIdx.x, wid = tid>>5, lane = tid&31;
    const int gid = lane>>2, tig = lane&3;
    const int l8 = lane&7, lb1 = (lane>>3)&1, lb2 = lane>>4;

    uint32_t* usm = (uint32_t*)sm;
    // zero pads: cols 56-63 (words 28-31) all rows; rows 56-63 cols 0-55
    for(int i = tid; i < 4*64*4; i += 128){
        int arr = i >> 8, rem = i & 255;
        int r = rem >> 2, j = rem & 3;
        usm[arr*64*36 + r*36 + 28 + j] = 0;
    }
    for(int i = tid; i < 4*8*28; i += 128){
        int arr = i / 224, rem = i - arr*224;
        int r = 56 + rem/28, j = rem - (rem/28)*28;
        usm[arr*64*36 + r*36 + j] = 0;
    }
    const uint32_t smB = smem_u32(sm);
    // group 1: Q -> B1, K -> B2
    {
        const __half* s0 = lqh + base_q;
        const __half* s1 = kvsh + base_k;
        for(int i = tid; i < 56*7; i += 128){
            int r = i/7, chx = i - r*7;
            asm volatile("cp.async.cg.shared.global [%0], [%1], 16;"
                :: "r"(smB + (0*64*STR + r*STR + chx*8)*2), "l"(s0 + (size_t)r*HH + chx*8));
            asm volatile("cp.async.cg.shared.global [%0], [%1], 16;"
                :: "r"(smB + (1*64*STR + r*STR + chx*8)*2), "l"(s1 + (size_t)r*HH + chx*8));
        }
        asm volatile("cp.async.commit_group;" ::: "memory");
    }
    // group 2: GK -> B3, GV -> B4
    {
        const __half* s2 = kvfqh + base_k;
        const __half* s3 = kvfqh + base_v;
        for(int i = tid; i < 56*7; i += 128){
            int r = i/7, chx = i - r*7;
            asm volatile("cp.async.cg.shared.global [%0], [%1], 16;"
                :: "r"(smB + (2*64*STR + r*STR + chx*8)*2), "l"(s2 + (size_t)r*HH + chx*8));
            asm volatile("cp.async.cg.shared.global [%0], [%1], 16;"
                :: "r"(smB + (3*64*STR + r*STR + chx*8)*2), "l"(s3 + (size_t)r*HH + chx*8));
        }
        asm volatile("cp.async.commit_group;" ::: "memory");
    }
    asm volatile("cp.async.wait_group 1;" ::: "memory");   // Q,K ready
    __syncthreads();

    const uint32_t qB = smem_u32(sB1), kB = smem_u32(sB2);
    const uint32_t gkB = smem_u32(sB3), gvB = smem_u32(sB4);
    const int m0 = wid*16;
    const uint32_t aOff = (uint32_t)(((m0 + l8 + lb1*8)*STR)*2);
    const uint32_t bRowN = (uint32_t)((l8 + lb2*8)*STR*2);

    // ---- S = Q @ K^T ----
    float c[8][4];
    #pragma unroll
    for(int n=0;n<8;n++){ c[n][0]=0; c[n][1]=0; c[n][2]=0; c[n][3]=0; }
    #pragma unroll
    for(int kk = 0; kk < 64; kk += 16){
        uint32_t a0,a1,a2,a3;
        ldsm4(a0,a1,a2,a3, qB + aOff + (kk + lb2*8)*2);
        uint32_t bb[8][2];
        #pragma unroll
        for(int np=0;np<4;np++){
            uint32_t addr = kB + bRowN + (uint32_t)((np*16*STR + kk + lb1*8)*2);
            ldsm4(bb[2*np][0], bb[2*np][1], bb[2*np+1][0], bb[2*np+1][1], addr);
        }
        #pragma unroll
        for(int n=0;n<8;n++)
            mma16(c[n], a0,a1,a2,a3, bb[n][0], bb[n][1]);
    }

    // ---- local softmax, P -> B1 (warp-private rows) ----
    #pragma unroll
    for(int half_=0; half_<2; half_++){
        const int h2 = half_*2;
        float m = -1e30f;
        #pragma unroll
        for(int n=0;n<7;n++) m = fmaxf(m, fmaxf(c[n][h2], c[n][h2+1]));
        m = fmaxf(m, __shfl_xor_sync(0xffffffffu, m, 1));
        m = fmaxf(m, __shfl_xor_sync(0xffffffffu, m, 2));
        float s = 0.f;
        #pragma unroll
        for(int n=0;n<7;n++){
            float e0 = __expf((c[n][h2  ] - m)*SCALEV);
            float e1 = __expf((c[n][h2+1] - m)*SCALEV);
            c[n][h2]=e0; c[n][h2+1]=e1; s += e0+e1;
        }
        s += __shfl_xor_sync(0xffffffffu, s, 1);
        s += __shfl_xor_sync(0xffffffffu, s, 2);
        const float inv = 1.f/s;
        const int row = m0 + gid + half_*8;
        #pragma unroll
        for(int n=0;n<8;n++){
            __half2 hv = (n<7) ? __floats2half2_rn(c[n][h2]*inv, c[n][h2+1]*inv)
                               : __floats2half2_rn(0.f, 0.f);
            *reinterpret_cast<__half2*>(sB1 + row*STR + n*8 + 2*tig) = hv;
        }
    }

    __syncthreads();   // all warps done reading K (B2)

    // group 3: V -> B2 (overlaps with GS softmax)
    {
        const __half* s1 = kvsh + base_v;
        for(int i = tid; i < 56*7; i += 128){
            int r = i/7, chx = i - r*7;
            asm volatile("cp.async.cg.shared.global [%0], [%1], 16;"
                :: "r"(smB + (1*64*STR + r*STR + chx*8)*2), "l"(s1 + (size_t)r*HH + chx*8));
        }
        asm volatile("cp.async.commit_group;" ::: "memory");
    }
    asm volatile("cp.async.wait_group 1;" ::: "memory");   // GK,GV ready
    __syncthreads();

    // ---- global softmax on B3 (warp-private rows) ----
    {
        const float gq = gqs[bc];
        #pragma unroll
        for(int half_=0; half_<2; half_++){
            const int row = m0 + gid + half_*8;
            float v[7][2];
            float m = -1e30f;
            #pragma unroll
            for(int n=0;n<7;n++){
                __half2 hv = *reinterpret_cast<__half2*>(sB3 + row*STR + n*8 + 2*tig);
                v[n][0] = gq*__low2float(hv);
                v[n][1] = gq*__high2float(hv);
                m = fmaxf(m, fmaxf(v[n][0], v[n][1]));
            }
            m = fmaxf(m, __shfl_xor_sync(0xffffffffu, m, 1));
            m = fmaxf(m, __shfl_xor_sync(0xffffffffu, m, 2));
            float s = 0.f;
            #pragma unroll
            for(int n=0;n<7;n++){
                v[n][0]=__expf(v[n][0]-m); v[n][1]=__expf(v[n][1]-m);
                s += v[n][0]+v[n][1];
            }
            s += __shfl_xor_sync(0xffffffffu, s, 1);
            s += __shfl_xor_sync(0xffffffffu, s, 2);
            const float inv = 1.f/s;
            #pragma unroll
            for(int n=0;n<8;n++){
                __half2 hv = (n<7) ? __floats2half2_rn(v[n][0]*inv, v[n][1]*inv)
                                   : __floats2half2_rn(0.f, 0.f);
                *reinterpret_cast<__half2*>(sB3 + row*STR + n*8 + 2*tig) = hv;
            }
        }
    }
    asm volatile("cp.async.wait_group 0;" ::: "memory");   // V ready
    __syncthreads();

    // ---- O = P@V^T + GS@GV^T ----
    #pragma unroll
    for(int n=0;n<8;n++){ c[n][0]=0; c[n][1]=0; c[n][2]=0; c[n][3]=0; }
    #pragma unroll
    for(int kk = 0; kk < 64; kk += 16){
        uint32_t a0,a1,a2,a3;
        ldsm4(a0,a1,a2,a3, qB + aOff + (kk + lb2*8)*2);
        uint32_t bb[8][2];
        #pragma unroll
        for(int np=0;np<4;np++){
            int nc = np*16;
            uint32_t addr = kB + (uint32_t)(((kk + lb1*8 + l8)*STR + nc + lb2*8)*2);
            ldsm4t(bb[2*np][0], bb[2*np][1], bb[2*np+1][0], bb[2*np+1][1], addr);
        }
        #pragma unroll
        for(int n=0;n<8;n++)
            mma16(c[n], a0,a1,a2,a3, bb[n][0], bb[n][1]);
    }
    #pragma unroll
    for(int kk = 0; kk < 64; kk += 16){
        uint32_t a0,a1,a2,a3;
        ldsm4(a0,a1,a2,a3, gkB + aOff + (kk + lb2*8)*2);
        uint32_t bb[8][2];
        #pragma unroll
        for(int np=0;np<4;np++){
            int nc = np*16;
            uint32_t addr = gvB + (uint32_t)(((kk + lb1*8 + l8)*STR + nc + lb2*8)*2);
            ldsm4t(bb[2*np][0], bb[2*np][1], bb[2*np+1][0], bb[2*np+1][1], addr);
        }
        #pragma unroll
        for(int n=0;n<8;n++)
            mma16(c[n], a0,a1,a2,a3, bb[n][0], bb[n][1]);
    }

    #pragma unroll
    for(int half_=0; half_<2; half_++){
        const int row = m0 + gid + half_*8;
        if(row < 56){
            #pragma unroll
            for(int n=0;n<7;n++){
                *reinterpret_cast<__half2*>(fH + base_q + row*HH + n*8 + 2*tig)
                    = __floats2half2_rn(c[n][half_*2], c[n][half_*2+1]);
            }
        }
    }
}

// ================= merged setup =================
#define NCVT  12544
#define NPREP 704
#define NBORD 3648
#define NMEAN 4096

__global__ void setup_kernel(const float* __restrict__ x_s, const float* __restrict__ x_fq,
                             const float* __restrict__ x_mt,
                             const float* __restrict__ lk_w, const float* __restrict__ lv_w,
                             const float* __restrict__ gk_w, const float* __restrict__ gv_w,
                             const float* __restrict__ la_w1, const float* __restrict__ la_w2,
                             const float* __restrict__ c1_w,
                             const float* __restrict__ lk_b, const float* __restrict__ gk_b,
                             const float* __restrict__ c1_b,
                             float* __restrict__ out)
{
    __shared__ float red[256];
    const int blk = blockIdx.x, tid = threadIdx.x;

    if(blk < NCVT){
        const int idx = blk*256 + tid;
        float4 v = reinterpret_cast<const float4*>(x_s)[idx];
        __half2 h0 = __floats2half2_rn(v.x, v.y);
        __half2 h1 = __floats2half2_rn(v.z, v.w);
        uint2 o;
        o.x = *reinterpret_cast<uint32_t*>(&h0);
        o.y = *reinterpret_cast<uint32_t*>(&h1);
        reinterpret_cast<uint2*>(g_xH)[idx] = o;
        float4 w = reinterpret_cast<const float4*>(x_fq)[idx];
        __half2 g0 = __floats2half2_rn(w.x, w.y);
        __half2 g1 = __floats2half2_rn(w.z, w.w);
        uint2 o2;
        o2.x = *reinterpret_cast<uint32_t*>(&g0);
        o2.y = *reinterpret_cast<uint32_t*>(&g1);
        reinterpret_cast<uint2*>(g_xH + NXE)[idx] = o2;
    } else if(blk < NCVT + NPREP){
        const int i = (blk - NCVT)*256 + tid;
        if(i < 131072){
            g_wh[i]          = __float2half(i < 65536 ? lk_w[i] : lv_w[i-65536]);
            g_wh[131072 + i] = __float2half(i < 65536 ? gk_w[i] : gv_w[i-65536]);
        } else if(i < 163840){
            int j = i - 131072;
            int row = j >> 8, col = j & 255;
            g_wh[262144 + j] = (row < ICC) ? __float2half(la_w1[row*CC + col])
                                           : __float2half(0.f);
        } else if(i < 180224){
            int j = i - 163840;
            g_wh[294912 + j] = __float2half(la_w2[j]);
        }
        if(i < 65536) g_wh[311296 + i] = __float2half(c1_w[i]);
        if(i < 512){
            g_sb[i]       = (i < 256) ? lk_b[i] : 0.f;
            g_sb[512 + i] = (i < 256) ? gk_b[i] : 0.f;
        }
    } else if(blk < NCVT + NPREP + NBORD){
        const int idx = (blk - NCVT - NPREP)*256 + tid;
        const int total = BB*CC*228;
        if(idx < total){
            const int bc = idx / 228, j = idx - bc*228;
            int h, w;
            if(j < 58){ h = 0; w = j; }
            else if(j < 116){ h = 57; w = j - 58; }
            else { int j2 = j - 116; h = 1 + (j2 >> 1); w = (j2 & 1) * 57; }
            out[((size_t)bc*OUTH + h)*OUTH + w] = c1_b[bc & 255];
        }
    } else {
        const int bc = blk - NCVT - NPREP - NBORD;
        const float* p = x_mt + (size_t)bc*PP;
        float s = 0.f;
        for(int i = tid; i < PP; i += 256) s += p[i];
        red[tid] = s; __syncthreads();
        for(int o = 128; o > 0; o >>= 1){
            if(tid < o) red[tid] += red[tid + o];
            __syncthreads();
        }
        if(tid == 0) g_xbar[bc] = red[0]*(1.0f/PP);
    }
}

// ---------------- launch ----------------
extern "C" void kernel_launch(void* const* d_in, const int* in_sizes, int n_in,
                              void* d_out, int out_size)
{
    const float* x_s  =(const float*)d_in[0];
    const float* x_fq =(const float*)d_in[1];
    const float* x_mt =(const float*)d_in[2];
    const float* la_w1=(const float*)d_in[3];
    const float* la_b1=(const float*)d_in[4];
    const float* la_g1=(const float*)d_in[5];
    const float* la_be1=(const float*)d_in[6];
    const float* la_w2=(const float*)d_in[7];
    const float* la_b2=(const float*)d_in[8];
    const float* la_g2=(const float*)d_in[9];
    const float* la_be2=(const float*)d_in[10];
    const float* lk_w =(const float*)d_in[11];
    const float* lk_b =(const float*)d_in[12];
    const float* lv_w =(const float*)d_in[13];
    const float* ga_w1=(const float*)d_in[14];
    const float* ga_b1=(const float*)d_in[15];
    const float* ga_g1=(const float*)d_in[16];
    const float* ga_be1=(const float*)d_in[17];
    const float* ga_w2=(const float*)d_in[18];
    const float* ga_b2=(const float*)d_in[19];
    const float* ga_g2=(const float*)d_in[20];
    const float* ga_be2=(const float*)d_in[21];
    const float* gk_w =(const float*)d_in[22];
    const float* gk_b =(const float*)d_in[23];
    const float* gv_w =(const float*)d_in[24];
    const float* c11_w=(const float*)d_in[25];
    const float* c11_b=(const float*)d_in[26];
    const float* c1_w =(const float*)d_in[27];
    const float* c1_b =(const float*)d_in[28];
    float* out=(float*)d_out;

    __half *t1H,*lqh,*kv,*fH,*wh;
    float *gqs;
    cudaGetSymbolAddress((void**)&t1H, g_t1H);
    cudaGetSymbolAddress((void**)&lqh, g_lqh);
    cudaGetSymbolAddress((void**)&kv,  g_kv);
    cudaGetSymbolAddress((void**)&fH,  g_fH);
    cudaGetSymbolAddress((void**)&gqs, g_gqs);
    cudaGetSymbolAddress((void**)&wh,  g_wh);

    const int NB = (PP + 127)/128;   // 25
    const int SM128 = 2*(128*72 + 64*136)*2;
    cudaFuncSetAttribute(mega_kernel,       cudaFuncAttributeMaxDynamicSharedMemorySize, SM128);
    cudaFuncSetAttribute(hgemm<EPI_BN_H>,   cudaFuncAttributeMaxDynamicSharedMemorySize, SM128);
    cudaFuncSetAttribute(hgemm<EPI_PAD>,    cudaFuncAttributeMaxDynamicSharedMemorySize, SM128);

    // 1: merged setup
    setup_kernel<<<NCVT + NPREP + NBORD + NMEAN, 256>>>(
        x_s, x_fq, x_mt, lk_w, lv_w, gk_w, gv_w, la_w1, la_w2, c1_w,
        lk_b, gk_b, c1_b, out);
    // 2: mega (KV + t1 + gq)
    {   dim3 g(NB, 6, 2*BB);
        mega_kernel<<<g, 128, SM128>>>(la_b1, la_g1, la_be1,
                                       c11_w, c11_b, ga_w1, ga_b1, ga_g1, ga_be1,
                                       ga_w2, ga_b2, ga_g2, ga_be2);
    }
    // 3: l_q
    {   dim3 g(NB, CC/128, BB);
        hgemm<EPI_BN_H><<<g, 128, SM128>>>(wh + 294912, t1H, lqh, ICC, CC,
                                           la_b2, la_g2, la_be2);
    }
    // 4: attention  <-- profiled
    attn_tc<<<BB*CC, 128>>>(lqh, kv, kv + KVN, gqs, fH);
    // 5: padded output conv
    {   dim3 g(NB, CC/128, BB);
        hgemm<EPI_PAD><<<g, 128, SM128>>>(wh + 311296, fH, out, CC, CC,
                                          c1_b, c1_b, c1_b);
    }
}